// round 4
// baseline (speedup 1.0000x reference)
#include <cuda_runtime.h>
#include <cstddef>

// ---------------------------------------------------------------------------
// SAGE 2-layer: CSR-based mean aggregation + fused dual-input SGEMM epilogues.
// Layer 1: h  = relu( mean_agg(x, E1) @ Wl1 + x[:N1] @ Wr1 + b1 )   [50000,256]
// Layer 2: out =      mean_agg(h, E2) @ Wl2 + h[:N2] @ Wr2 + b2     [10000,256]
// ---------------------------------------------------------------------------

static constexpr int cN0 = 200000;
static constexpr int cN1 = 50000;
static constexpr int cN2 = 10000;
static constexpr int cE1 = 1000000;
static constexpr int cE2 = 250000;
static constexpr int cCIN = 128;
static constexpr int cH = 256;

// ---- static device scratch (no runtime allocation allowed) ----
__device__ int   g_off1[cN1 + 1];
__device__ int   g_cur1[cN1];
__device__ int   g_adj1[cE1];                 // stores SRC node ids, CSR-ordered by dst
__device__ float g_agg1[(size_t)cN1 * cCIN];  // 25.6 MB
__device__ float g_h[(size_t)cN1 * cH];       // 51.2 MB
__device__ int   g_off2[cN2 + 1];
__device__ int   g_cur2[cN2];
__device__ int   g_adj2[cE2];
__device__ float g_agg2[(size_t)cN2 * cH];    // 10.2 MB

// ---------------------------------------------------------------------------
// small utility kernels
// ---------------------------------------------------------------------------
__global__ void k_zero_i32(int* __restrict__ p, int n) {
    int i = blockIdx.x * blockDim.x + threadIdx.x;
    if (i < n) p[i] = 0;
}

__global__ void k_hist(const int* __restrict__ dst, int E, int* __restrict__ off) {
    int i = blockIdx.x * blockDim.x + threadIdx.x;
    if (i < E) atomicAdd(&off[dst[i] + 1], 1);
}

// single-block inclusive scan (n up to ~64k is trivial)
__global__ void k_scan(int* __restrict__ a, int n) {
    __shared__ int s[1024];
    __shared__ int carry;
    int tid = threadIdx.x;
    if (tid == 0) carry = 0;
    __syncthreads();
    for (int base = 0; base < n; base += 1024) {
        int i = base + tid;
        int v = (i < n) ? a[i] : 0;
        s[tid] = v;
        __syncthreads();
        #pragma unroll
        for (int off = 1; off < 1024; off <<= 1) {
            int t = (tid >= off) ? s[tid - off] : 0;
            __syncthreads();
            s[tid] += t;
            __syncthreads();
        }
        if (i < n) a[i] = s[tid] + carry;
        __syncthreads();
        if (tid == 0) carry += s[1023];
        __syncthreads();
    }
}

__global__ void k_copy_i32(const int* __restrict__ src, int* __restrict__ dst, int n) {
    int i = blockIdx.x * blockDim.x + threadIdx.x;
    if (i < n) dst[i] = src[i];
}

// scatter edges into CSR slots; store the SOURCE node id directly (one less indirection)
__global__ void k_scatter(const int* __restrict__ src, const int* __restrict__ dst, int E,
                          int* __restrict__ cur, int* __restrict__ adj) {
    int i = blockIdx.x * blockDim.x + threadIdx.x;
    if (i < E) {
        int d = dst[i];
        int p = atomicAdd(&cur[d], 1);
        adj[p] = src[i];
    }
}

// ---------------------------------------------------------------------------
// mean aggregation: one warp per destination row.
// Feature width = NV * 128 floats (NV float4 per lane).
// ---------------------------------------------------------------------------
template <int NV>
__global__ void k_agg_mean(const float* __restrict__ feat, const int* __restrict__ adj,
                           const int* __restrict__ off, float* __restrict__ out, int nrows) {
    int row = blockIdx.x * blockDim.y + threadIdx.y;
    if (row >= nrows) return;
    int lane = threadIdx.x;
    int s0 = off[row];
    int s1 = off[row + 1];

    float4 acc[NV];
    #pragma unroll
    for (int c = 0; c < NV; ++c) acc[c] = make_float4(0.f, 0.f, 0.f, 0.f);

    for (int j = s0; j < s1; ++j) {
        int s = adj[j];  // broadcast load across warp
        const float4* xr = (const float4*)(feat + (size_t)s * (NV * 128));
        #pragma unroll
        for (int c = 0; c < NV; ++c) {
            float4 v = xr[lane + 32 * c];
            acc[c].x += v.x; acc[c].y += v.y; acc[c].z += v.z; acc[c].w += v.w;
        }
    }
    int deg = s1 - s0;
    float inv = 1.0f / (float)(deg > 0 ? deg : 1);
    float4* orow = (float4*)(out + (size_t)row * (NV * 128));
    #pragma unroll
    for (int c = 0; c < NV; ++c) {
        float4 r = acc[c];
        r.x *= inv; r.y *= inv; r.z *= inv; r.w *= inv;
        orow[lane + 32 * c] = r;
    }
}

// ---------------------------------------------------------------------------
// Dual-input SGEMM:  C[M,N] = [A1 | A2] @ [B1 ; B2] + bias, optional relu.
// A1:[M,K1], A2:[M,K2], B1:[K1,N], B2:[K2,N]. K1,K2 multiples of 16. N mult of 128.
// Block tile 128x128, BK=16, 256 threads, 8x8 micro-tile per thread.
// ---------------------------------------------------------------------------
__global__ void __launch_bounds__(256)
k_gemm_dual(const float* __restrict__ A1, const float* __restrict__ A2,
            const float* __restrict__ B1, const float* __restrict__ B2,
            const float* __restrict__ bias, float* __restrict__ C,
            int M, int K1, int K2, int N, int doRelu) {
    __shared__ float As[16][132];  // transposed A tile, padded (132*4B % 16B == 0 for LDS.128)
    __shared__ float Bs[16][128];

    int tid = threadIdx.x;
    int tx = tid & 15;        // 0..15 (column group)
    int ty = tid >> 4;        // 0..15 (row group)
    int bm = blockIdx.y * 128;
    int bn = blockIdx.x * 128;
    int Ktot = K1 + K2;

    float acc[8][8];
    #pragma unroll
    for (int i = 0; i < 8; ++i)
        #pragma unroll
        for (int j = 0; j < 8; ++j) acc[i][j] = 0.f;

    for (int kbase = 0; kbase < Ktot; kbase += 16) {
        // ---- load A tile (128 rows x 16 k), transposed into As ----
        const float* Asrc; int ldA, kcol;
        if (kbase < K1) { Asrc = A1; ldA = K1; kcol = kbase; }
        else            { Asrc = A2; ldA = K2; kcol = kbase - K1; }
        #pragma unroll
        for (int i = 0; i < 2; ++i) {
            int f = tid + 256 * i;        // 0..511
            int m = f >> 2;               // 0..127
            int k4 = (f & 3) << 2;        // 0,4,8,12
            int gm = bm + m;
            float4 v = make_float4(0.f, 0.f, 0.f, 0.f);
            if (gm < M) v = *(const float4*)(Asrc + (size_t)gm * ldA + kcol + k4);
            As[k4 + 0][m] = v.x;
            As[k4 + 1][m] = v.y;
            As[k4 + 2][m] = v.z;
            As[k4 + 3][m] = v.w;
        }
        // ---- load B tile (16 k x 128 n) ----
        const float* Bsrc; int kb;
        if (kbase < K1) { Bsrc = B1; kb = kbase; }
        else            { Bsrc = B2; kb = kbase - K1; }
        #pragma unroll
        for (int i = 0; i < 2; ++i) {
            int f = tid + 256 * i;
            int k = f >> 5;               // 0..15
            int n4 = (f & 31) << 2;       // 0..124
            *(float4*)&Bs[k][n4] = *(const float4*)(Bsrc + (size_t)(kb + k) * N + bn + n4);
        }
        __syncthreads();

        // ---- compute ----
        #pragma unroll
        for (int k = 0; k < 16; ++k) {
            float4 a0 = *(const float4*)&As[k][ty * 8];
            float4 a1 = *(const float4*)&As[k][ty * 8 + 4];
            float4 b0 = *(const float4*)&Bs[k][tx * 8];
            float4 b1 = *(const float4*)&Bs[k][tx * 8 + 4];
            float a[8] = {a0.x, a0.y, a0.z, a0.w, a1.x, a1.y, a1.z, a1.w};
            float b[8] = {b0.x, b0.y, b0.z, b0.w, b1.x, b1.y, b1.z, b1.w};
            #pragma unroll
            for (int i = 0; i < 8; ++i)
                #pragma unroll
                for (int j = 0; j < 8; ++j)
                    acc[i][j] = fmaf(a[i], b[j], acc[i][j]);
        }
        __syncthreads();
    }

    // ---- epilogue: + bias, optional relu, store ----
    float bv[8];
    #pragma unroll
    for (int j = 0; j < 8; ++j) bv[j] = bias[bn + tx * 8 + j];

    #pragma unroll
    for (int i = 0; i < 8; ++i) {
        int gm = bm + ty * 8 + i;
        if (gm >= M) continue;
        float4 r0, r1;
        r0.x = acc[i][0] + bv[0]; r0.y = acc[i][1] + bv[1];
        r0.z = acc[i][2] + bv[2]; r0.w = acc[i][3] + bv[3];
        r1.x = acc[i][4] + bv[4]; r1.y = acc[i][5] + bv[5];
        r1.z = acc[i][6] + bv[6]; r1.w = acc[i][7] + bv[7];
        if (doRelu) {
            r0.x = fmaxf(r0.x, 0.f); r0.y = fmaxf(r0.y, 0.f);
            r0.z = fmaxf(r0.z, 0.f); r0.w = fmaxf(r0.w, 0.f);
            r1.x = fmaxf(r1.x, 0.f); r1.y = fmaxf(r1.y, 0.f);
            r1.z = fmaxf(r1.z, 0.f); r1.w = fmaxf(r1.w, 0.f);
        }
        float* crow = C + (size_t)gm * N + bn + tx * 8;
        *(float4*)(crow)     = r0;
        *(float4*)(crow + 4) = r1;
    }
}

// ---------------------------------------------------------------------------
// host side
// ---------------------------------------------------------------------------
extern "C" void kernel_launch(void* const* d_in, const int* in_sizes, int n_in,
                              void* d_out, int out_size) {
    (void)in_sizes; (void)n_in; (void)out_size;

    const float* x    = (const float*)d_in[0];
    const int*   src1 = (const int*)d_in[1];
    const int*   dst1 = (const int*)d_in[2];
    const int*   src2 = (const int*)d_in[3];
    const int*   dst2 = (const int*)d_in[4];
    const float* Wl1  = (const float*)d_in[5];
    const float* Wr1  = (const float*)d_in[6];
    const float* b1   = (const float*)d_in[7];
    const float* Wl2  = (const float*)d_in[8];
    const float* Wr2  = (const float*)d_in[9];
    const float* b2   = (const float*)d_in[10];
    float* out = (float*)d_out;

    int *off1, *cur1, *adj1, *off2, *cur2, *adj2;
    float *agg1, *h, *agg2;
    cudaGetSymbolAddress((void**)&off1, g_off1);
    cudaGetSymbolAddress((void**)&cur1, g_cur1);
    cudaGetSymbolAddress((void**)&adj1, g_adj1);
    cudaGetSymbolAddress((void**)&agg1, g_agg1);
    cudaGetSymbolAddress((void**)&h,    g_h);
    cudaGetSymbolAddress((void**)&off2, g_off2);
    cudaGetSymbolAddress((void**)&cur2, g_cur2);
    cudaGetSymbolAddress((void**)&adj2, g_adj2);
    cudaGetSymbolAddress((void**)&agg2, g_agg2);

    // ---------------- layer 1 ----------------
    k_zero_i32<<<(cN1 + 1 + 255) / 256, 256>>>(off1, cN1 + 1);
    k_hist<<<(cE1 + 255) / 256, 256>>>(dst1, cE1, off1);
    k_scan<<<1, 1024>>>(off1, cN1 + 1);
    k_copy_i32<<<(cN1 + 255) / 256, 256>>>(off1, cur1, cN1);
    k_scatter<<<(cE1 + 255) / 256, 256>>>(src1, dst1, cE1, cur1, adj1);

    k_agg_mean<1><<<(cN1 + 7) / 8, dim3(32, 8)>>>(x, adj1, off1, agg1, cN1);

    // h = relu([agg1 | x[:N1]] @ [Wl1;Wr1] + b1)
    k_gemm_dual<<<dim3(cH / 128, (cN1 + 127) / 128), 256>>>(
        agg1, x, Wl1, Wr1, b1, h, cN1, cCIN, cCIN, cH, 1);

    // ---------------- layer 2 ----------------
    k_zero_i32<<<(cN2 + 1 + 255) / 256, 256>>>(off2, cN2 + 1);
    k_hist<<<(cE2 + 255) / 256, 256>>>(dst2, cE2, off2);
    k_scan<<<1, 1024>>>(off2, cN2 + 1);
    k_copy_i32<<<(cN2 + 255) / 256, 256>>>(off2, cur2, cN2);
    k_scatter<<<(cE2 + 255) / 256, 256>>>(src2, dst2, cE2, cur2, adj2);

    k_agg_mean<2><<<(cN2 + 7) / 8, dim3(32, 8)>>>(h, adj2, off2, agg2, cN2);

    // out = [agg2 | h[:N2]] @ [Wl2;Wr2] + b2
    k_gemm_dual<<<dim3(cH / 128, (cN2 + 127) / 128), 256>>>(
        agg2, h, Wl2, Wr2, b2, out, cN2, cH, cH, cH, 0);
}

// round 8
// speedup vs baseline: 1.7995x; 1.7995x over previous
#include <cuda_runtime.h>
#include <cstddef>

// ---------------------------------------------------------------------------
// SAGE 2-layer: CSR mean aggregation + tf32 tensor-core dual-input GEMMs.
// Layer 1: h   = relu([agg1 | x[:N1]] @ [Wl1;Wr1] + b1)   [50000,256]
// Layer 2: out =      [agg2 | h[:N2]] @ [Wl2;Wr2] + b2    [10000,256]
// ---------------------------------------------------------------------------

static constexpr int cN0 = 200000;
static constexpr int cN1 = 50000;
static constexpr int cN2 = 10000;
static constexpr int cE1 = 1000000;
static constexpr int cE2 = 250000;
static constexpr int cCIN = 128;
static constexpr int cH = 256;

// ---- static device scratch ----
__device__ int   g_off1[cN1 + 1];
__device__ int   g_cur1[cN1];
__device__ int   g_adj1[cE1];
__device__ float g_agg1[(size_t)cN1 * cCIN];
__device__ float g_h[(size_t)cN1 * cH];
__device__ int   g_off2[cN2 + 1];
__device__ int   g_cur2[cN2];
__device__ int   g_adj2[cE2];
__device__ float g_agg2[(size_t)cN2 * cH];

// ---------------------------------------------------------------------------
// utility kernels
// ---------------------------------------------------------------------------
__global__ void k_zero_i32(int* __restrict__ p, int n) {
    int i = blockIdx.x * blockDim.x + threadIdx.x;
    if (i < n) p[i] = 0;
}

__global__ void k_hist(const int* __restrict__ dst, int E, int* __restrict__ off) {
    int i = blockIdx.x * blockDim.x + threadIdx.x;
    if (i < E) atomicAdd(&off[dst[i] + 1], 1);
}

// single-block inclusive scan (shuffle-based), also emits cur = start offsets
__global__ void k_scan_fused(int* __restrict__ a, int* __restrict__ cur, int n, int ncur) {
    __shared__ int wsum[32];
    __shared__ int carry;
    int tid = threadIdx.x, lane = tid & 31, wid = tid >> 5;
    if (tid == 0) carry = 0;
    __syncthreads();
    for (int base = 0; base < n; base += 1024) {
        int i = base + tid;
        int v = (i < n) ? a[i] : 0;
        int x = v;
        #pragma unroll
        for (int d = 1; d < 32; d <<= 1) {
            int t = __shfl_up_sync(0xffffffffu, x, d);
            if (lane >= d) x += t;
        }
        if (lane == 31) wsum[wid] = x;
        __syncthreads();
        if (wid == 0) {
            int s = wsum[lane];
            #pragma unroll
            for (int d = 1; d < 32; d <<= 1) {
                int t = __shfl_up_sync(0xffffffffu, s, d);
                if (lane >= d) s += t;
            }
            wsum[lane] = s;
        }
        __syncthreads();
        int inc = x + (wid > 0 ? wsum[wid - 1] : 0) + carry;
        if (i < n) a[i] = inc;
        if (i < ncur) cur[i] = inc;
        __syncthreads();
        if (tid == 1023) carry = inc;
        __syncthreads();
    }
}

__global__ void k_scatter(const int* __restrict__ src, const int* __restrict__ dst, int E,
                          int* __restrict__ cur, int* __restrict__ adj) {
    int i = blockIdx.x * blockDim.x + threadIdx.x;
    if (i < E) {
        int d = dst[i];
        int p = atomicAdd(&cur[d], 1);
        adj[p] = src[i];
    }
}

// ---------------------------------------------------------------------------
// mean aggregation: one warp per destination row, NV float4 per lane.
// ---------------------------------------------------------------------------
template <int NV>
__global__ void k_agg_mean(const float* __restrict__ feat, const int* __restrict__ adj,
                           const int* __restrict__ off, float* __restrict__ out, int nrows) {
    int row = blockIdx.x * blockDim.y + threadIdx.y;
    if (row >= nrows) return;
    int lane = threadIdx.x;
    int s0 = off[row];
    int s1 = off[row + 1];

    float4 acc[NV];
    #pragma unroll
    for (int c = 0; c < NV; ++c) acc[c] = make_float4(0.f, 0.f, 0.f, 0.f);

    for (int j = s0; j < s1; ++j) {
        int s = adj[j];
        const float4* xr = (const float4*)(feat + (size_t)s * (NV * 128));
        #pragma unroll
        for (int c = 0; c < NV; ++c) {
            float4 v = xr[lane + 32 * c];
            acc[c].x += v.x; acc[c].y += v.y; acc[c].z += v.z; acc[c].w += v.w;
        }
    }
    int deg = s1 - s0;
    float inv = 1.0f / (float)(deg > 0 ? deg : 1);
    float4* orow = (float4*)(out + (size_t)row * (NV * 128));
    #pragma unroll
    for (int c = 0; c < NV; ++c) {
        float4 r = acc[c];
        r.x *= inv; r.y *= inv; r.z *= inv; r.w *= inv;
        orow[lane + 32 * c] = r;
    }
}

// ---------------------------------------------------------------------------
// tf32 tensor-core dual-input GEMM:
//   C[M,N] = [A1 | A2] @ [B1 ; B2] + bias, optional relu.
// Block tile 128x128, BK=16, 256 threads (8 warps, 2x4), warp tile 64x32.
// ---------------------------------------------------------------------------
__device__ __forceinline__ float tf32r(float x) {
    unsigned u;
    asm("cvt.rna.tf32.f32 %0, %1;" : "=r"(u) : "f"(x));
    return __uint_as_float(u);
}

__device__ __forceinline__ void mma_tf32(float* c, const unsigned* a, const unsigned* b) {
    asm volatile(
        "mma.sync.aligned.m16n8k8.row.col.f32.tf32.tf32.f32 "
        "{%0,%1,%2,%3}, {%4,%5,%6,%7}, {%8,%9}, {%0,%1,%2,%3};"
        : "+f"(c[0]), "+f"(c[1]), "+f"(c[2]), "+f"(c[3])
        : "r"(a[0]), "r"(a[1]), "r"(a[2]), "r"(a[3]), "r"(b[0]), "r"(b[1]));
}

__global__ void __launch_bounds__(256, 2)
k_gemm_dual_tc(const float* __restrict__ A1, const float* __restrict__ A2,
               const float* __restrict__ B1, const float* __restrict__ B2,
               const float* __restrict__ bias, float* __restrict__ C,
               int M, int K1, int K2, int N, int doRelu) {
    __shared__ float As[16 * 136];   // As[k][m ^ ((k>>2)<<3)], stride 136
    __shared__ float Bs[16 * 136];   // Bs[k][n], stride 136

    int tid  = threadIdx.x;
    int lane = tid & 31;
    int warp = tid >> 5;
    int wm = warp >> 2;        // 0..1
    int wn = warp & 3;         // 0..3
    int g  = lane >> 2;        // 0..7
    int tg = lane & 3;         // 0..3
    int bm = blockIdx.y * 128;
    int bn = blockIdx.x * 128;
    int Ktot = K1 + K2;

    float acc[4][4][4];
    #pragma unroll
    for (int mt = 0; mt < 4; ++mt)
        #pragma unroll
        for (int nt = 0; nt < 4; ++nt)
            #pragma unroll
            for (int c = 0; c < 4; ++c) acc[mt][nt][c] = 0.f;

    // staging thread mapping
    int am  = tid >> 2;            // 0..63 (A rows, +64 second pass)
    int ak4 = (tid & 3) << 2;      // 0,4,8,12 (A k-start of float4)
    int bk  = tid >> 5;            // 0..7 (B k-rows, +8 second pass)
    int bn4 = (tid & 31) << 2;     // 0..124 (B n-start of float4)

    for (int kb = 0; kb < Ktot; kb += 16) {
        const float* Asrc; int ldA, kcol;
        const float* Bsrc; int kbb;
        if (kb < K1) { Asrc = A1; ldA = K1; kcol = kb;      Bsrc = B1; kbb = kb; }
        else         { Asrc = A2; ldA = K2; kcol = kb - K1; Bsrc = B2; kbb = kb - K1; }

        // issue global loads early (overlap with previous tile's compute)
        float4 av[2], bv[2];
        #pragma unroll
        for (int i = 0; i < 2; ++i) {
            int gm = bm + am + 64 * i;
            av[i] = (gm < M) ? *(const float4*)(Asrc + (size_t)gm * ldA + kcol + ak4)
                             : make_float4(0.f, 0.f, 0.f, 0.f);
        }
        #pragma unroll
        for (int i = 0; i < 2; ++i) {
            int k = bk + 8 * i;
            bv[i] = *(const float4*)(Bsrc + (size_t)(kbb + k) * N + bn + bn4);
        }

        __syncthreads();  // previous compute done before overwriting smem

        #pragma unroll
        for (int i = 0; i < 2; ++i) {
            int m = am + 64 * i;
            float vv[4] = {av[i].x, av[i].y, av[i].z, av[i].w};
            #pragma unroll
            for (int j = 0; j < 4; ++j) {
                int k = ak4 + j;
                As[k * 136 + (m ^ ((k >> 2) << 3))] = tf32r(vv[j]);
            }
        }
        #pragma unroll
        for (int i = 0; i < 2; ++i) {
            int k = bk + 8 * i;
            float4 v = bv[i];
            v.x = tf32r(v.x); v.y = tf32r(v.y); v.z = tf32r(v.z); v.w = tf32r(v.w);
            *(float4*)&Bs[k * 136 + bn4] = v;
        }

        __syncthreads();

        #pragma unroll
        for (int k8 = 0; k8 < 16; k8 += 8) {
            unsigned a[4][4], b[4][2];
            int kA = k8 + tg;
            int kB = k8 + tg + 4;
            int sA = (kA >> 2) << 3;
            int sB = (kB >> 2) << 3;
            #pragma unroll
            for (int mt = 0; mt < 4; ++mt) {
                int m0 = wm * 64 + mt * 16 + g;
                a[mt][0] = __float_as_uint(As[kA * 136 + ( m0      ^ sA)]);
                a[mt][1] = __float_as_uint(As[kA * 136 + ((m0 + 8) ^ sA)]);
                a[mt][2] = __float_as_uint(As[kB * 136 + ( m0      ^ sB)]);
                a[mt][3] = __float_as_uint(As[kB * 136 + ((m0 + 8) ^ sB)]);
            }
            #pragma unroll
            for (int nt = 0; nt < 4; ++nt) {
                int n0 = wn * 32 + nt * 8 + g;
                b[nt][0] = __float_as_uint(Bs[kA * 136 + n0]);
                b[nt][1] = __float_as_uint(Bs[kB * 136 + n0]);
            }
            #pragma unroll
            for (int mt = 0; mt < 4; ++mt)
                #pragma unroll
                for (int nt = 0; nt < 4; ++nt)
                    mma_tf32(acc[mt][nt], a[mt], b[nt]);
        }
    }

    // ---- epilogue: bias (+relu), store float2 per fragment half ----
    #pragma unroll
    for (int nt = 0; nt < 4; ++nt) {
        int col = bn + wn * 32 + nt * 8 + tg * 2;
        float2 bb = *(const float2*)&bias[col];
        #pragma unroll
        for (int mt = 0; mt < 4; ++mt) {
            int row_lo = bm + wm * 64 + mt * 16 + g;
            int row_hi = row_lo + 8;
            float2 lo = make_float2(acc[mt][nt][0] + bb.x, acc[mt][nt][1] + bb.y);
            float2 hi = make_float2(acc[mt][nt][2] + bb.x, acc[mt][nt][3] + bb.y);
            if (doRelu) {
                lo.x = fmaxf(lo.x, 0.f); lo.y = fmaxf(lo.y, 0.f);
                hi.x = fmaxf(hi.x, 0.f); hi.y = fmaxf(hi.y, 0.f);
            }
            if (row_lo < M) *(float2*)&C[(size_t)row_lo * N + col] = lo;
            if (row_hi < M) *(float2*)&C[(size_t)row_hi * N + col] = hi;
        }
    }
}

// ---------------------------------------------------------------------------
// host side
// ---------------------------------------------------------------------------
extern "C" void kernel_launch(void* const* d_in, const int* in_sizes, int n_in,
                              void* d_out, int out_size) {
    (void)in_sizes; (void)n_in; (void)out_size;

    const float* x    = (const float*)d_in[0];
    const int*   src1 = (const int*)d_in[1];
    const int*   dst1 = (const int*)d_in[2];
    const int*   src2 = (const int*)d_in[3];
    const int*   dst2 = (const int*)d_in[4];
    const float* Wl1  = (const float*)d_in[5];
    const float* Wr1  = (const float*)d_in[6];
    const float* b1   = (const float*)d_in[7];
    const float* Wl2  = (const float*)d_in[8];
    const float* Wr2  = (const float*)d_in[9];
    const float* b2   = (const float*)d_in[10];
    float* out = (float*)d_out;

    int *off1, *cur1, *adj1, *off2, *cur2, *adj2;
    float *agg1, *h, *agg2;
    cudaGetSymbolAddress((void**)&off1, g_off1);
    cudaGetSymbolAddress((void**)&cur1, g_cur1);
    cudaGetSymbolAddress((void**)&adj1, g_adj1);
    cudaGetSymbolAddress((void**)&agg1, g_agg1);
    cudaGetSymbolAddress((void**)&h,    g_h);
    cudaGetSymbolAddress((void**)&off2, g_off2);
    cudaGetSymbolAddress((void**)&cur2, g_cur2);
    cudaGetSymbolAddress((void**)&adj2, g_adj2);
    cudaGetSymbolAddress((void**)&agg2, g_agg2);

    // ---------------- layer 1 ----------------
    k_zero_i32<<<(cN1 + 1 + 255) / 256, 256>>>(off1, cN1 + 1);
    k_hist<<<(cE1 + 255) / 256, 256>>>(dst1, cE1, off1);
    k_scan_fused<<<1, 1024>>>(off1, cur1, cN1 + 1, cN1);
    k_scatter<<<(cE1 + 255) / 256, 256>>>(src1, dst1, cE1, cur1, adj1);

    k_agg_mean<1><<<(cN1 + 7) / 8, dim3(32, 8)>>>(x, adj1, off1, agg1, cN1);

    k_gemm_dual_tc<<<dim3(cH / 128, (cN1 + 127) / 128), 256>>>(
        agg1, x, Wl1, Wr1, b1, h, cN1, cCIN, cCIN, cH, 1);

    // ---------------- layer 2 ----------------
    k_zero_i32<<<(cN2 + 1 + 255) / 256, 256>>>(off2, cN2 + 1);
    k_hist<<<(cE2 + 255) / 256, 256>>>(dst2, cE2, off2);
    k_scan_fused<<<1, 1024>>>(off2, cur2, cN2 + 1, cN2);
    k_scatter<<<(cE2 + 255) / 256, 256>>>(src2, dst2, cE2, cur2, adj2);

    k_agg_mean<2><<<(cN2 + 7) / 8, dim3(32, 8)>>>(h, adj2, off2, agg2, cN2);

    k_gemm_dual_tc<<<dim3(cH / 128, (cN2 + 127) / 128), 256>>>(
        agg2, h, Wl2, Wr2, b2, out, cN2, cH, cH, cH, 0);
}

// round 9
// speedup vs baseline: 1.8692x; 1.0387x over previous
#include <cuda_runtime.h>
#include <cstddef>

// ---------------------------------------------------------------------------
// SAGE 2-layer: CSR mean aggregation + tf32 tensor-core dual-input GEMMs.
// R8: double-buffered GEMM pipeline, MLP-4 aggregation, MLP-4 CSR build.
// ---------------------------------------------------------------------------

static constexpr int cN0 = 200000;
static constexpr int cN1 = 50000;
static constexpr int cN2 = 10000;
static constexpr int cE1 = 1000000;
static constexpr int cE2 = 250000;
static constexpr int cCIN = 128;
static constexpr int cH = 256;

// ---- static device scratch ----
__device__ int   g_off1[cN1 + 1];
__device__ int   g_cur1[cN1];
__device__ int   g_adj1[cE1];
__device__ float g_agg1[(size_t)cN1 * cCIN];
__device__ float g_h[(size_t)cN1 * cH];
__device__ int   g_off2[cN2 + 1];
__device__ int   g_cur2[cN2];
__device__ int   g_adj2[cE2];
__device__ float g_agg2[(size_t)cN2 * cH];

// ---------------------------------------------------------------------------
// CSR build kernels
// ---------------------------------------------------------------------------
__global__ void k_zero_both(int* __restrict__ p1, int n1, int* __restrict__ p2, int n2) {
    int i = blockIdx.x * blockDim.x + threadIdx.x;
    if (i < n1) p1[i] = 0;
    if (i < n2) p2[i] = 0;
}

// 4 edges per thread -> 4 independent atomics in flight
__global__ void k_hist4(const int* __restrict__ dst, int E, int* __restrict__ off) {
    int i = (blockIdx.x * blockDim.x + threadIdx.x) * 4;
    if (i + 4 <= E) {
        int4 d = *(const int4*)(dst + i);
        atomicAdd(&off[d.x + 1], 1);
        atomicAdd(&off[d.y + 1], 1);
        atomicAdd(&off[d.z + 1], 1);
        atomicAdd(&off[d.w + 1], 1);
    } else {
        for (int j = i; j < E; ++j) atomicAdd(&off[dst[j] + 1], 1);
    }
}

// single-block inclusive scan, 4 elements/thread; also emits cur = segment starts
__global__ void k_scan_fused(int* __restrict__ a, int* __restrict__ cur, int n, int ncur) {
    __shared__ int wsum[32];
    __shared__ int carry;
    int tid = threadIdx.x, lane = tid & 31, wid = tid >> 5;
    if (tid == 0) carry = 0;
    __syncthreads();
    for (int base = 0; base < n; base += 4096) {
        int i0 = base + tid * 4;
        int v0 = (i0 + 0 < n) ? a[i0 + 0] : 0;
        int v1 = (i0 + 1 < n) ? a[i0 + 1] : 0;
        int v2 = (i0 + 2 < n) ? a[i0 + 2] : 0;
        int v3 = (i0 + 3 < n) ? a[i0 + 3] : 0;
        int l1 = v0 + v1, l2 = l1 + v2, l3 = l2 + v3;  // local inclusive
        int x = l3;                                     // thread sum
        #pragma unroll
        for (int d = 1; d < 32; d <<= 1) {
            int t = __shfl_up_sync(0xffffffffu, x, d);
            if (lane >= d) x += t;
        }
        if (lane == 31) wsum[wid] = x;
        __syncthreads();
        if (wid == 0) {
            int s = wsum[lane];
            #pragma unroll
            for (int d = 1; d < 32; d <<= 1) {
                int t = __shfl_up_sync(0xffffffffu, s, d);
                if (lane >= d) s += t;
            }
            wsum[lane] = s;
        }
        __syncthreads();
        int pre = x - l3 + (wid > 0 ? wsum[wid - 1] : 0) + carry;  // exclusive prefix
        int o0 = pre + v0, o1 = pre + l1, o2 = pre + l2, o3 = pre + l3;
        if (i0 + 0 < n) a[i0 + 0] = o0;
        if (i0 + 1 < n) a[i0 + 1] = o1;
        if (i0 + 2 < n) a[i0 + 2] = o2;
        if (i0 + 3 < n) a[i0 + 3] = o3;
        if (i0 + 0 < ncur) cur[i0 + 0] = o0;
        if (i0 + 1 < ncur) cur[i0 + 1] = o1;
        if (i0 + 2 < ncur) cur[i0 + 2] = o2;
        if (i0 + 3 < ncur) cur[i0 + 3] = o3;
        __syncthreads();
        if (tid == 1023) carry = pre + l3;
        __syncthreads();
    }
}

// 4 edges per thread -> 4 independent atomic+store pairs in flight
__global__ void k_scatter4(const int* __restrict__ src, const int* __restrict__ dst, int E,
                           int* __restrict__ cur, int* __restrict__ adj) {
    int i = (blockIdx.x * blockDim.x + threadIdx.x) * 4;
    if (i + 4 <= E) {
        int4 s = *(const int4*)(src + i);
        int4 d = *(const int4*)(dst + i);
        int p0 = atomicAdd(&cur[d.x], 1);
        int p1 = atomicAdd(&cur[d.y], 1);
        int p2 = atomicAdd(&cur[d.z], 1);
        int p3 = atomicAdd(&cur[d.w], 1);
        adj[p0] = s.x; adj[p1] = s.y; adj[p2] = s.z; adj[p3] = s.w;
    } else {
        for (int j = i; j < E; ++j) {
            int p = atomicAdd(&cur[dst[j]], 1);
            adj[p] = src[j];
        }
    }
}

// ---------------------------------------------------------------------------
// mean aggregation: one warp per destination row, NV float4 per lane.
// Process 4 edges per iteration for MLP.
// ---------------------------------------------------------------------------
template <int NV>
__global__ void k_agg_mean(const float* __restrict__ feat, const int* __restrict__ adj,
                           const int* __restrict__ off, float* __restrict__ out, int nrows) {
    int row = blockIdx.x * blockDim.y + threadIdx.y;
    if (row >= nrows) return;
    int lane = threadIdx.x;
    int s0 = off[row];
    int s1 = off[row + 1];

    float4 acc[NV];
    #pragma unroll
    for (int c = 0; c < NV; ++c) acc[c] = make_float4(0.f, 0.f, 0.f, 0.f);

    int j = s0;
    for (; j + 4 <= s1; j += 4) {
        int i0 = adj[j], i1 = adj[j + 1], i2 = adj[j + 2], i3 = adj[j + 3];
        const float4* x0 = (const float4*)(feat + (size_t)i0 * (NV * 128));
        const float4* x1 = (const float4*)(feat + (size_t)i1 * (NV * 128));
        const float4* x2 = (const float4*)(feat + (size_t)i2 * (NV * 128));
        const float4* x3 = (const float4*)(feat + (size_t)i3 * (NV * 128));
        #pragma unroll
        for (int c = 0; c < NV; ++c) {
            float4 v0 = x0[lane + 32 * c];
            float4 v1 = x1[lane + 32 * c];
            float4 v2 = x2[lane + 32 * c];
            float4 v3 = x3[lane + 32 * c];
            acc[c].x += (v0.x + v1.x) + (v2.x + v3.x);
            acc[c].y += (v0.y + v1.y) + (v2.y + v3.y);
            acc[c].z += (v0.z + v1.z) + (v2.z + v3.z);
            acc[c].w += (v0.w + v1.w) + (v2.w + v3.w);
        }
    }
    for (; j < s1; ++j) {
        int s = adj[j];
        const float4* xr = (const float4*)(feat + (size_t)s * (NV * 128));
        #pragma unroll
        for (int c = 0; c < NV; ++c) {
            float4 v = xr[lane + 32 * c];
            acc[c].x += v.x; acc[c].y += v.y; acc[c].z += v.z; acc[c].w += v.w;
        }
    }
    int deg = s1 - s0;
    float inv = 1.0f / (float)(deg > 0 ? deg : 1);
    float4* orow = (float4*)(out + (size_t)row * (NV * 128));
    #pragma unroll
    for (int c = 0; c < NV; ++c) {
        float4 r = acc[c];
        r.x *= inv; r.y *= inv; r.z *= inv; r.w *= inv;
        orow[lane + 32 * c] = r;
    }
}

// ---------------------------------------------------------------------------
// tf32 tensor-core dual-input GEMM, double-buffered smem pipeline:
//   C[M,N] = [A1 | A2] @ [B1 ; B2] + bias, optional relu.
// Block tile 128x128, BK=16, 256 threads (8 warps 2x4), warp tile 64x32.
// Schedule per tile: LDG(t+1) -> compute(t) -> STS(t+1) -> syncthreads.
// ---------------------------------------------------------------------------
__device__ __forceinline__ float tf32r(float x) {
    unsigned u;
    asm("cvt.rna.tf32.f32 %0, %1;" : "=r"(u) : "f"(x));
    return __uint_as_float(u);
}

__device__ __forceinline__ void mma_tf32(float* c, const unsigned* a, const unsigned* b) {
    asm volatile(
        "mma.sync.aligned.m16n8k8.row.col.f32.tf32.tf32.f32 "
        "{%0,%1,%2,%3}, {%4,%5,%6,%7}, {%8,%9}, {%0,%1,%2,%3};"
        : "+f"(c[0]), "+f"(c[1]), "+f"(c[2]), "+f"(c[3])
        : "r"(a[0]), "r"(a[1]), "r"(a[2]), "r"(a[3]), "r"(b[0]), "r"(b[1]));
}

__global__ void __launch_bounds__(256, 2)
k_gemm_dual_tc(const float* __restrict__ A1, const float* __restrict__ A2,
               const float* __restrict__ B1, const float* __restrict__ B2,
               const float* __restrict__ bias, float* __restrict__ C,
               int M, int K1, int K2, int N, int doRelu) {
    __shared__ float As[2][16 * 136];   // As[buf][k*136 + (m ^ ((k>>2)<<3))]
    __shared__ float Bs[2][16 * 136];   // Bs[buf][k*136 + n]

    int tid  = threadIdx.x;
    int lane = tid & 31;
    int warp = tid >> 5;
    int wm = warp >> 2;        // 0..1
    int wn = warp & 3;         // 0..3
    int g  = lane >> 2;        // 0..7
    int tg = lane & 3;         // 0..3
    int bm = blockIdx.y * 128;
    int bn = blockIdx.x * 128;
    int Ktot = K1 + K2;
    int ntiles = Ktot >> 4;

    float acc[4][4][4];
    #pragma unroll
    for (int mt = 0; mt < 4; ++mt)
        #pragma unroll
        for (int nt = 0; nt < 4; ++nt)
            #pragma unroll
            for (int c = 0; c < 4; ++c) acc[mt][nt][c] = 0.f;

    // staging thread mapping
    int am  = tid >> 2;            // 0..63 (A rows, +64 second pass)
    int ak4 = (tid & 3) << 2;      // 0,4,8,12
    int bk  = tid >> 5;            // 0..7 (B k-rows, +8 second pass)
    int bn4 = (tid & 31) << 2;     // 0..124

    float4 av[2], bv[2];

    // ---- LDG for tile t into registers ----
    auto ldg_tile = [&](int t) {
        int kb = t << 4;
        const float* Asrc; int ldA, kcol;
        const float* Bsrc; int kbb;
        if (kb < K1) { Asrc = A1; ldA = K1; kcol = kb;      Bsrc = B1; kbb = kb; }
        else         { Asrc = A2; ldA = K2; kcol = kb - K1; Bsrc = B2; kbb = kb - K1; }
        #pragma unroll
        for (int i = 0; i < 2; ++i) {
            int gm = bm + am + 64 * i;
            av[i] = (gm < M) ? *(const float4*)(Asrc + (size_t)gm * ldA + kcol + ak4)
                             : make_float4(0.f, 0.f, 0.f, 0.f);
        }
        #pragma unroll
        for (int i = 0; i < 2; ++i) {
            int k = bk + 8 * i;
            bv[i] = *(const float4*)(Bsrc + (size_t)(kbb + k) * N + bn + bn4);
        }
    };

    // ---- STS registers into buffer b (with tf32 rounding + A swizzle) ----
    auto sts_tile = [&](int b) {
        #pragma unroll
        for (int i = 0; i < 2; ++i) {
            int m = am + 64 * i;
            float vv[4] = {av[i].x, av[i].y, av[i].z, av[i].w};
            #pragma unroll
            for (int j = 0; j < 4; ++j) {
                int k = ak4 + j;
                As[b][k * 136 + (m ^ ((k >> 2) << 3))] = tf32r(vv[j]);
            }
        }
        #pragma unroll
        for (int i = 0; i < 2; ++i) {
            int k = bk + 8 * i;
            float4 v = bv[i];
            v.x = tf32r(v.x); v.y = tf32r(v.y); v.z = tf32r(v.z); v.w = tf32r(v.w);
            *(float4*)&Bs[b][k * 136 + bn4] = v;
        }
    };

    // ---- MMAs over buffer b ----
    auto compute_tile = [&](int b) {
        #pragma unroll
        for (int k8 = 0; k8 < 16; k8 += 8) {
            unsigned a[4][4], bb[4][2];
            int kA = k8 + tg;
            int kB = k8 + tg + 4;
            int sA = (kA >> 2) << 3;
            int sB = (kB >> 2) << 3;
            #pragma unroll
            for (int mt = 0; mt < 4; ++mt) {
                int m0 = wm * 64 + mt * 16 + g;
                a[mt][0] = __float_as_uint(As[b][kA * 136 + ( m0      ^ sA)]);
                a[mt][1] = __float_as_uint(As[b][kA * 136 + ((m0 + 8) ^ sA)]);
                a[mt][2] = __float_as_uint(As[b][kB * 136 + ( m0      ^ sB)]);
                a[mt][3] = __float_as_uint(As[b][kB * 136 + ((m0 + 8) ^ sB)]);
            }
            #pragma unroll
            for (int nt = 0; nt < 4; ++nt) {
                int n0 = wn * 32 + nt * 8 + g;
                bb[nt][0] = __float_as_uint(Bs[b][kA * 136 + n0]);
                bb[nt][1] = __float_as_uint(Bs[b][kB * 136 + n0]);
            }
            #pragma unroll
            for (int mt = 0; mt < 4; ++mt)
                #pragma unroll
                for (int nt = 0; nt < 4; ++nt)
                    mma_tf32(acc[mt][nt], a[mt], bb[nt]);
        }
    };

    // ---- pipelined main loop ----
    ldg_tile(0);
    sts_tile(0);
    __syncthreads();

    for (int t = 0; t < ntiles; ++t) {
        int cur = t & 1;
        if (t + 1 < ntiles) ldg_tile(t + 1);   // issue next-tile GMEM loads
        compute_tile(cur);                      // covered by these LDGs
        if (t + 1 < ntiles) {
            sts_tile(cur ^ 1);
            __syncthreads();
        }
    }

    // ---- epilogue: bias (+relu), store float2 per fragment half ----
    #pragma unroll
    for (int nt = 0; nt < 4; ++nt) {
        int col = bn + wn * 32 + nt * 8 + tg * 2;
        float2 bb = *(const float2*)&bias[col];
        #pragma unroll
        for (int mt = 0; mt < 4; ++mt) {
            int row_lo = bm + wm * 64 + mt * 16 + g;
            int row_hi = row_lo + 8;
            float2 lo = make_float2(acc[mt][nt][0] + bb.x, acc[mt][nt][1] + bb.y);
            float2 hi = make_float2(acc[mt][nt][2] + bb.x, acc[mt][nt][3] + bb.y);
            if (doRelu) {
                lo.x = fmaxf(lo.x, 0.f); lo.y = fmaxf(lo.y, 0.f);
                hi.x = fmaxf(hi.x, 0.f); hi.y = fmaxf(hi.y, 0.f);
            }
            if (row_lo < M) *(float2*)&C[(size_t)row_lo * N + col] = lo;
            if (row_hi < M) *(float2*)&C[(size_t)row_hi * N + col] = hi;
        }
    }
}

// ---------------------------------------------------------------------------
// host side
// ---------------------------------------------------------------------------
extern "C" void kernel_launch(void* const* d_in, const int* in_sizes, int n_in,
                              void* d_out, int out_size) {
    (void)in_sizes; (void)n_in; (void)out_size;

    const float* x    = (const float*)d_in[0];
    const int*   src1 = (const int*)d_in[1];
    const int*   dst1 = (const int*)d_in[2];
    const int*   src2 = (const int*)d_in[3];
    const int*   dst2 = (const int*)d_in[4];
    const float* Wl1  = (const float*)d_in[5];
    const float* Wr1  = (const float*)d_in[6];
    const float* b1   = (const float*)d_in[7];
    const float* Wl2  = (const float*)d_in[8];
    const float* Wr2  = (const float*)d_in[9];
    const float* b2   = (const float*)d_in[10];
    float* out = (float*)d_out;

    int *off1, *cur1, *adj1, *off2, *cur2, *adj2;
    float *agg1, *h, *agg2;
    cudaGetSymbolAddress((void**)&off1, g_off1);
    cudaGetSymbolAddress((void**)&cur1, g_cur1);
    cudaGetSymbolAddress((void**)&adj1, g_adj1);
    cudaGetSymbolAddress((void**)&agg1, g_agg1);
    cudaGetSymbolAddress((void**)&h,    g_h);
    cudaGetSymbolAddress((void**)&off2, g_off2);
    cudaGetSymbolAddress((void**)&cur2, g_cur2);
    cudaGetSymbolAddress((void**)&adj2, g_adj2);
    cudaGetSymbolAddress((void**)&agg2, g_agg2);

    // ---- CSR builds (independent of features) ----
    k_zero_both<<<(cN1 + 1 + 255) / 256, 256>>>(off1, cN1 + 1, off2, cN2 + 1);
    k_hist4<<<(cE1 / 4 + 255) / 256, 256>>>(dst1, cE1, off1);
    k_hist4<<<(cE2 / 4 + 255) / 256, 256>>>(dst2, cE2, off2);
    k_scan_fused<<<1, 1024>>>(off1, cur1, cN1 + 1, cN1);
    k_scan_fused<<<1, 1024>>>(off2, cur2, cN2 + 1, cN2);
    k_scatter4<<<(cE1 / 4 + 255) / 256, 256>>>(src1, dst1, cE1, cur1, adj1);
    k_scatter4<<<(cE2 / 4 + 255) / 256, 256>>>(src2, dst2, cE2, cur2, adj2);

    // ---- layer 1 ----
    k_agg_mean<1><<<(cN1 + 7) / 8, dim3(32, 8)>>>(x, adj1, off1, agg1, cN1);
    k_gemm_dual_tc<<<dim3(cH / 128, (cN1 + 127) / 128), 256>>>(
        agg1, x, Wl1, Wr1, b1, h, cN1, cCIN, cCIN, cH, 1);

    // ---- layer 2 ----
    k_agg_mean<2><<<(cN2 + 7) / 8, dim3(32, 8)>>>(h, adj2, off2, agg2, cN2);
    k_gemm_dual_tc<<<dim3(cH / 128, (cN2 + 127) / 128), 256>>>(
        agg2, h, Wl2, Wr2, b2, out, cN2, cH, cH, cH, 0);
}

// round 10
// speedup vs baseline: 2.2210x; 1.1882x over previous
#include <cuda_runtime.h>
#include <cstddef>

// ---------------------------------------------------------------------------
// SAGE 2-layer: CSR mean aggregation + tf32 tensor-core dual-input GEMMs.
// R9: multi-block 3-pass scan (both layers fused), fused hist/scatter.
// ---------------------------------------------------------------------------

static constexpr int cN0 = 200000;
static constexpr int cN1 = 50000;
static constexpr int cN2 = 10000;
static constexpr int cE1 = 1000000;
static constexpr int cE2 = 250000;
static constexpr int cCIN = 128;
static constexpr int cH = 256;

static constexpr int SCAN_CHUNK = 1024;                       // elems per block
static constexpr int SB1 = (cN1 + 1 + SCAN_CHUNK - 1) / SCAN_CHUNK;  // 49
static constexpr int SB2 = (cN2 + 1 + SCAN_CHUNK - 1) / SCAN_CHUNK;  // 10

// ---- static device scratch ----
__device__ int   g_off1[cN1 + 1];
__device__ int   g_cur1[cN1];
__device__ int   g_adj1[cE1];
__device__ float g_agg1[(size_t)cN1 * cCIN];
__device__ float g_h[(size_t)cN1 * cH];
__device__ int   g_off2[cN2 + 1];
__device__ int   g_cur2[cN2];
__device__ int   g_adj2[cE2];
__device__ float g_agg2[(size_t)cN2 * cH];
__device__ int   g_part1[SB1];
__device__ int   g_part2[SB2];

// ---------------------------------------------------------------------------
// CSR build kernels
// ---------------------------------------------------------------------------
__global__ void k_zero_both(int* __restrict__ p1, int n1, int* __restrict__ p2, int n2) {
    int i = blockIdx.x * blockDim.x + threadIdx.x;
    if (i < n1) p1[i] = 0;
    if (i < n2) p2[i] = 0;
}

// fused histogram for both edge lists; 4 edges per thread
__global__ void k_hist_both(const int* __restrict__ dst1, int E1, int* __restrict__ off1, int nb1,
                            const int* __restrict__ dst2, int E2, int* __restrict__ off2) {
    const int* dst; int E; int* off; int b;
    if (blockIdx.x < nb1) { dst = dst1; E = E1; off = off1; b = blockIdx.x; }
    else                  { dst = dst2; E = E2; off = off2; b = blockIdx.x - nb1; }
    int i = (b * blockDim.x + threadIdx.x) * 4;
    if (i + 4 <= E) {
        int4 d = *(const int4*)(dst + i);
        atomicAdd(&off[d.x + 1], 1);
        atomicAdd(&off[d.y + 1], 1);
        atomicAdd(&off[d.z + 1], 1);
        atomicAdd(&off[d.w + 1], 1);
    } else {
        for (int j = i; j < E; ++j) atomicAdd(&off[dst[j] + 1], 1);
    }
}

// ---- multi-block scan, pass 1: per-block local inclusive scan + block totals
__global__ void k_scan_pass1(int* __restrict__ a1, int n1, int* __restrict__ p1, int nb1,
                             int* __restrict__ a2, int n2, int* __restrict__ p2) {
    __shared__ int wsum[8];
    int* a; int n; int* p; int bb;
    if ((int)blockIdx.x < nb1) { a = a1; n = n1; p = p1; bb = blockIdx.x; }
    else                       { a = a2; n = n2; p = p2; bb = blockIdx.x - nb1; }

    int tid = threadIdx.x, lane = tid & 31, wid = tid >> 5;   // 256 threads, 8 warps
    int i0 = bb * SCAN_CHUNK + tid * 4;

    int v0 = (i0 + 0 < n) ? a[i0 + 0] : 0;
    int v1 = (i0 + 1 < n) ? a[i0 + 1] : 0;
    int v2 = (i0 + 2 < n) ? a[i0 + 2] : 0;
    int v3 = (i0 + 3 < n) ? a[i0 + 3] : 0;
    int l1 = v0 + v1, l2 = l1 + v2, l3 = l2 + v3;

    int x = l3;
    #pragma unroll
    for (int d = 1; d < 32; d <<= 1) {
        int t = __shfl_up_sync(0xffffffffu, x, d);
        if (lane >= d) x += t;
    }
    if (lane == 31) wsum[wid] = x;
    __syncthreads();
    if (wid == 0 && lane < 8) {
        int s = wsum[lane];
        #pragma unroll
        for (int d = 1; d < 8; d <<= 1) {
            int t = __shfl_up_sync(0x000000ffu, s, d);
            if (lane >= d) s += t;
        }
        wsum[lane] = s;
    }
    __syncthreads();
    int pre = x - l3 + (wid > 0 ? wsum[wid - 1] : 0);   // block-local exclusive prefix

    if (i0 + 0 < n) a[i0 + 0] = pre + v0;
    if (i0 + 1 < n) a[i0 + 1] = pre + l1;
    if (i0 + 2 < n) a[i0 + 2] = pre + l2;
    if (i0 + 3 < n) a[i0 + 3] = pre + l3;
    if (tid == 255) p[bb] = pre + l3;                   // block total
}

// ---- pass 2: one warp exclusive-scans both partials arrays in place
__device__ __forceinline__ void warp_excl_scan_inplace(int* p, int nb, int lane) {
    int carry = 0;
    for (int base = 0; base < nb; base += 32) {
        int i = base + lane;
        int v = (i < nb) ? p[i] : 0;
        int x = v;
        #pragma unroll
        for (int d = 1; d < 32; d <<= 1) {
            int t = __shfl_up_sync(0xffffffffu, x, d);
            if (lane >= d) x += t;
        }
        int total = __shfl_sync(0xffffffffu, x, 31);
        if (i < nb) p[i] = x - v + carry;               // exclusive
        carry += total;
    }
}

__global__ void k_scan_pass2(int* __restrict__ p1, int nb1, int* __restrict__ p2, int nb2) {
    int lane = threadIdx.x;
    warp_excl_scan_inplace(p1, nb1, lane);
    warp_excl_scan_inplace(p2, nb2, lane);
}

// ---- pass 3: add block prefixes; emit cur = segment starts
__global__ void k_scan_pass3(int* __restrict__ a1, int n1, const int* __restrict__ p1, int nb1,
                             int* __restrict__ cur1, int ncur1,
                             int* __restrict__ a2, int n2, const int* __restrict__ p2,
                             int* __restrict__ cur2, int ncur2) {
    int* a; int n; const int* p; int* cur; int ncur; int bb;
    if ((int)blockIdx.x < nb1) { a = a1; n = n1; p = p1; cur = cur1; ncur = ncur1; bb = blockIdx.x; }
    else                       { a = a2; n = n2; p = p2; cur = cur2; ncur = ncur2; bb = blockIdx.x - nb1; }
    int add = p[bb];
    int i0 = bb * SCAN_CHUNK + threadIdx.x * 4;
    #pragma unroll
    for (int j = 0; j < 4; ++j) {
        int i = i0 + j;
        if (i < n) {
            int v = a[i] + add;
            a[i] = v;
            if (i < ncur) cur[i] = v;
        }
    }
}

// fused scatter for both edge lists; 4 edges per thread
__global__ void k_scatter_both(const int* __restrict__ src1, const int* __restrict__ dst1, int E1,
                               int* __restrict__ cur1, int* __restrict__ adj1, int nb1,
                               const int* __restrict__ src2, const int* __restrict__ dst2, int E2,
                               int* __restrict__ cur2, int* __restrict__ adj2) {
    const int *src, *dst; int E; int *cur, *adj; int b;
    if (blockIdx.x < nb1) { src = src1; dst = dst1; E = E1; cur = cur1; adj = adj1; b = blockIdx.x; }
    else                  { src = src2; dst = dst2; E = E2; cur = cur2; adj = adj2; b = blockIdx.x - nb1; }
    int i = (b * blockDim.x + threadIdx.x) * 4;
    if (i + 4 <= E) {
        int4 s = *(const int4*)(src + i);
        int4 d = *(const int4*)(dst + i);
        int p0 = atomicAdd(&cur[d.x], 1);
        int p1 = atomicAdd(&cur[d.y], 1);
        int p2 = atomicAdd(&cur[d.z], 1);
        int p3 = atomicAdd(&cur[d.w], 1);
        adj[p0] = s.x; adj[p1] = s.y; adj[p2] = s.z; adj[p3] = s.w;
    } else {
        for (int j = i; j < E; ++j) {
            int p = atomicAdd(&cur[dst[j]], 1);
            adj[p] = src[j];
        }
    }
}

// ---------------------------------------------------------------------------
// mean aggregation: one warp per destination row, NV float4 per lane,
// 4 edges per iteration for MLP.
// ---------------------------------------------------------------------------
template <int NV>
__global__ void k_agg_mean(const float* __restrict__ feat, const int* __restrict__ adj,
                           const int* __restrict__ off, float* __restrict__ out, int nrows) {
    int row = blockIdx.x * blockDim.y + threadIdx.y;
    if (row >= nrows) return;
    int lane = threadIdx.x;
    int s0 = off[row];
    int s1 = off[row + 1];

    float4 acc[NV];
    #pragma unroll
    for (int c = 0; c < NV; ++c) acc[c] = make_float4(0.f, 0.f, 0.f, 0.f);

    int j = s0;
    for (; j + 4 <= s1; j += 4) {
        int i0 = adj[j], i1 = adj[j + 1], i2 = adj[j + 2], i3 = adj[j + 3];
        const float4* x0 = (const float4*)(feat + (size_t)i0 * (NV * 128));
        const float4* x1 = (const float4*)(feat + (size_t)i1 * (NV * 128));
        const float4* x2 = (const float4*)(feat + (size_t)i2 * (NV * 128));
        const float4* x3 = (const float4*)(feat + (size_t)i3 * (NV * 128));
        #pragma unroll
        for (int c = 0; c < NV; ++c) {
            float4 v0 = x0[lane + 32 * c];
            float4 v1 = x1[lane + 32 * c];
            float4 v2 = x2[lane + 32 * c];
            float4 v3 = x3[lane + 32 * c];
            acc[c].x += (v0.x + v1.x) + (v2.x + v3.x);
            acc[c].y += (v0.y + v1.y) + (v2.y + v3.y);
            acc[c].z += (v0.z + v1.z) + (v2.z + v3.z);
            acc[c].w += (v0.w + v1.w) + (v2.w + v3.w);
        }
    }
    for (; j < s1; ++j) {
        int s = adj[j];
        const float4* xr = (const float4*)(feat + (size_t)s * (NV * 128));
        #pragma unroll
        for (int c = 0; c < NV; ++c) {
            float4 v = xr[lane + 32 * c];
            acc[c].x += v.x; acc[c].y += v.y; acc[c].z += v.z; acc[c].w += v.w;
        }
    }
    int deg = s1 - s0;
    float inv = 1.0f / (float)(deg > 0 ? deg : 1);
    float4* orow = (float4*)(out + (size_t)row * (NV * 128));
    #pragma unroll
    for (int c = 0; c < NV; ++c) {
        float4 r = acc[c];
        r.x *= inv; r.y *= inv; r.z *= inv; r.w *= inv;
        orow[lane + 32 * c] = r;
    }
}

// ---------------------------------------------------------------------------
// tf32 tensor-core dual-input GEMM, double-buffered smem pipeline.
// ---------------------------------------------------------------------------
__device__ __forceinline__ float tf32r(float x) {
    unsigned u;
    asm("cvt.rna.tf32.f32 %0, %1;" : "=r"(u) : "f"(x));
    return __uint_as_float(u);
}

__device__ __forceinline__ void mma_tf32(float* c, const unsigned* a, const unsigned* b) {
    asm volatile(
        "mma.sync.aligned.m16n8k8.row.col.f32.tf32.tf32.f32 "
        "{%0,%1,%2,%3}, {%4,%5,%6,%7}, {%8,%9}, {%0,%1,%2,%3};"
        : "+f"(c[0]), "+f"(c[1]), "+f"(c[2]), "+f"(c[3])
        : "r"(a[0]), "r"(a[1]), "r"(a[2]), "r"(a[3]), "r"(b[0]), "r"(b[1]));
}

__global__ void __launch_bounds__(256, 2)
k_gemm_dual_tc(const float* __restrict__ A1, const float* __restrict__ A2,
               const float* __restrict__ B1, const float* __restrict__ B2,
               const float* __restrict__ bias, float* __restrict__ C,
               int M, int K1, int K2, int N, int doRelu) {
    __shared__ float As[2][16 * 136];
    __shared__ float Bs[2][16 * 136];

    int tid  = threadIdx.x;
    int lane = tid & 31;
    int warp = tid >> 5;
    int wm = warp >> 2;
    int wn = warp & 3;
    int g  = lane >> 2;
    int tg = lane & 3;
    int bm = blockIdx.y * 128;
    int bn = blockIdx.x * 128;
    int Ktot = K1 + K2;
    int ntiles = Ktot >> 4;

    float acc[4][4][4];
    #pragma unroll
    for (int mt = 0; mt < 4; ++mt)
        #pragma unroll
        for (int nt = 0; nt < 4; ++nt)
            #pragma unroll
            for (int c = 0; c < 4; ++c) acc[mt][nt][c] = 0.f;

    int am  = tid >> 2;
    int ak4 = (tid & 3) << 2;
    int bk  = tid >> 5;
    int bn4 = (tid & 31) << 2;

    float4 av[2], bv[2];

    auto ldg_tile = [&](int t) {
        int kb = t << 4;
        const float* Asrc; int ldA, kcol;
        const float* Bsrc; int kbb;
        if (kb < K1) { Asrc = A1; ldA = K1; kcol = kb;      Bsrc = B1; kbb = kb; }
        else         { Asrc = A2; ldA = K2; kcol = kb - K1; Bsrc = B2; kbb = kb - K1; }
        #pragma unroll
        for (int i = 0; i < 2; ++i) {
            int gm = bm + am + 64 * i;
            av[i] = (gm < M) ? *(const float4*)(Asrc + (size_t)gm * ldA + kcol + ak4)
                             : make_float4(0.f, 0.f, 0.f, 0.f);
        }
        #pragma unroll
        for (int i = 0; i < 2; ++i) {
            int k = bk + 8 * i;
            bv[i] = *(const float4*)(Bsrc + (size_t)(kbb + k) * N + bn + bn4);
        }
    };

    auto sts_tile = [&](int b) {
        #pragma unroll
        for (int i = 0; i < 2; ++i) {
            int m = am + 64 * i;
            float vv[4] = {av[i].x, av[i].y, av[i].z, av[i].w};
            #pragma unroll
            for (int j = 0; j < 4; ++j) {
                int k = ak4 + j;
                As[b][k * 136 + (m ^ ((k >> 2) << 3))] = tf32r(vv[j]);
            }
        }
        #pragma unroll
        for (int i = 0; i < 2; ++i) {
            int k = bk + 8 * i;
            float4 v = bv[i];
            v.x = tf32r(v.x); v.y = tf32r(v.y); v.z = tf32r(v.z); v.w = tf32r(v.w);
            *(float4*)&Bs[b][k * 136 + bn4] = v;
        }
    };

    auto compute_tile = [&](int b) {
        #pragma unroll
        for (int k8 = 0; k8 < 16; k8 += 8) {
            unsigned a[4][4], bb[4][2];
            int kA = k8 + tg;
            int kB = k8 + tg + 4;
            int sA = (kA >> 2) << 3;
            int sB = (kB >> 2) << 3;
            #pragma unroll
            for (int mt = 0; mt < 4; ++mt) {
                int m0 = wm * 64 + mt * 16 + g;
                a[mt][0] = __float_as_uint(As[b][kA * 136 + ( m0      ^ sA)]);
                a[mt][1] = __float_as_uint(As[b][kA * 136 + ((m0 + 8) ^ sA)]);
                a[mt][2] = __float_as_uint(As[b][kB * 136 + ( m0      ^ sB)]);
                a[mt][3] = __float_as_uint(As[b][kB * 136 + ((m0 + 8) ^ sB)]);
            }
            #pragma unroll
            for (int nt = 0; nt < 4; ++nt) {
                int n0 = wn * 32 + nt * 8 + g;
                bb[nt][0] = __float_as_uint(Bs[b][kA * 136 + n0]);
                bb[nt][1] = __float_as_uint(Bs[b][kB * 136 + n0]);
            }
            #pragma unroll
            for (int mt = 0; mt < 4; ++mt)
                #pragma unroll
                for (int nt = 0; nt < 4; ++nt)
                    mma_tf32(acc[mt][nt], a[mt], bb[nt]);
        }
    };

    ldg_tile(0);
    sts_tile(0);
    __syncthreads();

    for (int t = 0; t < ntiles; ++t) {
        int cur = t & 1;
        if (t + 1 < ntiles) ldg_tile(t + 1);
        compute_tile(cur);
        if (t + 1 < ntiles) {
            sts_tile(cur ^ 1);
            __syncthreads();
        }
    }

    #pragma unroll
    for (int nt = 0; nt < 4; ++nt) {
        int col = bn + wn * 32 + nt * 8 + tg * 2;
        float2 bb = *(const float2*)&bias[col];
        #pragma unroll
        for (int mt = 0; mt < 4; ++mt) {
            int row_lo = bm + wm * 64 + mt * 16 + g;
            int row_hi = row_lo + 8;
            float2 lo = make_float2(acc[mt][nt][0] + bb.x, acc[mt][nt][1] + bb.y);
            float2 hi = make_float2(acc[mt][nt][2] + bb.x, acc[mt][nt][3] + bb.y);
            if (doRelu) {
                lo.x = fmaxf(lo.x, 0.f); lo.y = fmaxf(lo.y, 0.f);
                hi.x = fmaxf(hi.x, 0.f); hi.y = fmaxf(hi.y, 0.f);
            }
            if (row_lo < M) *(float2*)&C[(size_t)row_lo * N + col] = lo;
            if (row_hi < M) *(float2*)&C[(size_t)row_hi * N + col] = hi;
        }
    }
}

// ---------------------------------------------------------------------------
// host side
// ---------------------------------------------------------------------------
extern "C" void kernel_launch(void* const* d_in, const int* in_sizes, int n_in,
                              void* d_out, int out_size) {
    (void)in_sizes; (void)n_in; (void)out_size;

    const float* x    = (const float*)d_in[0];
    const int*   src1 = (const int*)d_in[1];
    const int*   dst1 = (const int*)d_in[2];
    const int*   src2 = (const int*)d_in[3];
    const int*   dst2 = (const int*)d_in[4];
    const float* Wl1  = (const float*)d_in[5];
    const float* Wr1  = (const float*)d_in[6];
    const float* b1   = (const float*)d_in[7];
    const float* Wl2  = (const float*)d_in[8];
    const float* Wr2  = (const float*)d_in[9];
    const float* b2   = (const float*)d_in[10];
    float* out = (float*)d_out;

    int *off1, *cur1, *adj1, *off2, *cur2, *adj2, *part1, *part2;
    float *agg1, *h, *agg2;
    cudaGetSymbolAddress((void**)&off1, g_off1);
    cudaGetSymbolAddress((void**)&cur1, g_cur1);
    cudaGetSymbolAddress((void**)&adj1, g_adj1);
    cudaGetSymbolAddress((void**)&agg1, g_agg1);
    cudaGetSymbolAddress((void**)&h,    g_h);
    cudaGetSymbolAddress((void**)&off2, g_off2);
    cudaGetSymbolAddress((void**)&cur2, g_cur2);
    cudaGetSymbolAddress((void**)&adj2, g_adj2);
    cudaGetSymbolAddress((void**)&agg2, g_agg2);
    cudaGetSymbolAddress((void**)&part1, g_part1);
    cudaGetSymbolAddress((void**)&part2, g_part2);

    const int hb1 = (cE1 / 4 + 255) / 256;   // hist/scatter blocks, layer 1
    const int hb2 = (cE2 / 4 + 255) / 256;

    // ---- CSR builds (both layers, fused launches) ----
    k_zero_both<<<(cN1 + 1 + 255) / 256, 256>>>(off1, cN1 + 1, off2, cN2 + 1);
    k_hist_both<<<hb1 + hb2, 256>>>(dst1, cE1, off1, hb1, dst2, cE2, off2);
    k_scan_pass1<<<SB1 + SB2, 256>>>(off1, cN1 + 1, part1, SB1, off2, cN2 + 1, part2);
    k_scan_pass2<<<1, 32>>>(part1, SB1, part2, SB2);
    k_scan_pass3<<<SB1 + SB2, 256>>>(off1, cN1 + 1, part1, SB1, cur1, cN1,
                                     off2, cN2 + 1, part2, cur2, cN2);
    k_scatter_both<<<hb1 + hb2, 256>>>(src1, dst1, cE1, cur1, adj1, hb1,
                                       src2, dst2, cE2, cur2, adj2);

    // ---- layer 1 ----
    k_agg_mean<1><<<(cN1 + 7) / 8, dim3(32, 8)>>>(x, adj1, off1, agg1, cN1);
    k_gemm_dual_tc<<<dim3(cH / 128, (cN1 + 127) / 128), 256>>>(
        agg1, x, Wl1, Wr1, b1, h, cN1, cCIN, cCIN, cH, 1);

    // ---- layer 2 ----
    k_agg_mean<2><<<(cN2 + 7) / 8, dim3(32, 8)>>>(h, adj2, off2, agg2, cN2);
    k_gemm_dual_tc<<<dim3(cH / 128, (cN2 + 127) / 128), 256>>>(
        agg2, h, Wl2, Wr2, b2, out, cN2, cH, cH, cH, 0);
}

// round 11
// speedup vs baseline: 2.2823x; 1.0276x over previous
#include <cuda_runtime.h>
#include <cuda_fp16.h>
#include <cstddef>

// ---------------------------------------------------------------------------
// SAGE 2-layer. R10: fp16 feature gathers (fp32 accum), single-pass grid scan,
// x->fp16 convert fused into hist launch, h stored fp16 (== tf32 rounding).
// ---------------------------------------------------------------------------

static constexpr int cN0 = 200000;
static constexpr int cN1 = 50000;
static constexpr int cN2 = 10000;
static constexpr int cE1 = 1000000;
static constexpr int cE2 = 250000;
static constexpr int cCIN = 128;
static constexpr int cH = 256;

static constexpr int SCAN_CHUNK = 1024;
static constexpr int SB1 = (cN1 + 1 + SCAN_CHUNK - 1) / SCAN_CHUNK;  // 49
static constexpr int SB2 = (cN2 + 1 + SCAN_CHUNK - 1) / SCAN_CHUNK;  // 10

// ---- static device scratch ----
__device__ int    g_off1[cN1 + 1];
__device__ int    g_cur1[cN1];
__device__ int    g_adj1[cE1];
__device__ float  g_agg1[(size_t)cN1 * cCIN];
__device__ __half g_xh[(size_t)cN0 * cCIN];    // fp16 copy of x (51.2 MB)
__device__ __half g_h[(size_t)cN1 * cH];       // layer-1 output, fp16 (25.6 MB)
__device__ int    g_off2[cN2 + 1];
__device__ int    g_cur2[cN2];
__device__ int    g_adj2[cE2];
__device__ float  g_agg2[(size_t)cN2 * cH];
__device__ int    g_parts[SB1 + SB2];
__device__ int    g_scan_counter;

// ---------------------------------------------------------------------------
// zero off arrays + scan counter
// ---------------------------------------------------------------------------
__global__ void k_zero_both(int* __restrict__ p1, int n1, int* __restrict__ p2, int n2,
                            int* __restrict__ counter) {
    int i = blockIdx.x * blockDim.x + threadIdx.x;
    if (i < n1) p1[i] = 0;
    if (i < n2) p2[i] = 0;
    if (i == 0) *counter = 0;
}

// ---------------------------------------------------------------------------
// fused: histogram (both layers) + x -> fp16 conversion (extra blocks)
// ---------------------------------------------------------------------------
__global__ void k_hist_conv(const int* __restrict__ dst1, int E1, int* __restrict__ off1, int nb1,
                            const int* __restrict__ dst2, int E2, int* __restrict__ off2, int nb2,
                            const float* __restrict__ x, __half* __restrict__ xh, int nx) {
    int b = blockIdx.x;
    if (b >= nb1 + nb2) {
        // conversion blocks: 8 floats per thread, exact coverage
        int cb = b - (nb1 + nb2);
        int i = (cb * blockDim.x + threadIdx.x) * 8;
        if (i + 8 <= nx) {
            float4 a = *(const float4*)(x + i);
            float4 c = *(const float4*)(x + i + 4);
            __half2 h0 = __floats2half2_rn(a.x, a.y);
            __half2 h1 = __floats2half2_rn(a.z, a.w);
            __half2 h2 = __floats2half2_rn(c.x, c.y);
            __half2 h3 = __floats2half2_rn(c.z, c.w);
            uint4 packed;
            packed.x = *(unsigned*)&h0; packed.y = *(unsigned*)&h1;
            packed.z = *(unsigned*)&h2; packed.w = *(unsigned*)&h3;
            *(uint4*)(xh + i) = packed;
        }
        return;
    }
    const int* dst; int E; int* off;
    if (b < nb1) { dst = dst1; E = E1; off = off1; }
    else         { dst = dst2; E = E2; off = off2; b -= nb1; }
    int i = (b * blockDim.x + threadIdx.x) * 4;
    if (i + 4 <= E) {
        int4 d = *(const int4*)(dst + i);
        atomicAdd(&off[d.x + 1], 1);
        atomicAdd(&off[d.y + 1], 1);
        atomicAdd(&off[d.z + 1], 1);
        atomicAdd(&off[d.w + 1], 1);
    } else {
        for (int j = i; j < E; ++j) atomicAdd(&off[dst[j] + 1], 1);
    }
}

// ---------------------------------------------------------------------------
// single-pass scan: 59 blocks (single wave), grid-wide flag between phases.
// Scans off1 and off2 in place; emits cur1/cur2 = segment starts.
// ---------------------------------------------------------------------------
__global__ void k_scan_onepass(int* __restrict__ a1, int n1, int nb1,
                               int* __restrict__ cur1, int ncur1,
                               int* __restrict__ a2, int n2,
                               int* __restrict__ cur2, int ncur2,
                               int* __restrict__ parts, int* __restrict__ counter) {
    __shared__ int wsum[8];
    __shared__ int sprefix;
    int* a; int n; int* cur; int ncur; int bb; int pbase;
    if ((int)blockIdx.x < nb1) { a = a1; n = n1; cur = cur1; ncur = ncur1; bb = blockIdx.x; pbase = 0; }
    else                       { a = a2; n = n2; cur = cur2; ncur = ncur2; bb = blockIdx.x - nb1; pbase = nb1; }

    int tid = threadIdx.x, lane = tid & 31, wid = tid >> 5;
    int i0 = bb * SCAN_CHUNK + tid * 4;

    int v0 = (i0 + 0 < n) ? a[i0 + 0] : 0;
    int v1 = (i0 + 1 < n) ? a[i0 + 1] : 0;
    int v2 = (i0 + 2 < n) ? a[i0 + 2] : 0;
    int v3 = (i0 + 3 < n) ? a[i0 + 3] : 0;
    int l1 = v0 + v1, l2 = l1 + v2, l3 = l2 + v3;

    int x = l3;
    #pragma unroll
    for (int d = 1; d < 32; d <<= 1) {
        int t = __shfl_up_sync(0xffffffffu, x, d);
        if (lane >= d) x += t;
    }
    if (lane == 31) wsum[wid] = x;
    __syncthreads();
    if (wid == 0 && lane < 8) {
        int s = wsum[lane];
        #pragma unroll
        for (int d = 1; d < 8; d <<= 1) {
            int t = __shfl_up_sync(0x000000ffu, s, d);
            if (lane >= d) s += t;
        }
        wsum[lane] = s;
    }
    __syncthreads();
    int pre = x - l3 + (wid > 0 ? wsum[wid - 1] : 0);   // block-local exclusive prefix
    int o0 = pre + v0, o1 = pre + l1, o2 = pre + l2, o3 = pre + l3;

    // publish block total, then grid-wide rendezvous (single wave: 59 <= 148 SMs)
    if (tid == 255) {
        parts[pbase + bb] = pre + l3;
        __threadfence();
        atomicAdd(counter, 1);
    }
    if (tid == 0) {
        while (atomicAdd(counter, 0) < (int)gridDim.x) { }
    }
    __syncthreads();
    __threadfence();

    // prefix over preceding block totals within this segment (bb <= 48)
    if (tid < 32) {
        int s = 0;
        for (int j = lane; j < bb; j += 32) s += parts[pbase + j];
        #pragma unroll
        for (int d = 16; d > 0; d >>= 1) s += __shfl_xor_sync(0xffffffffu, s, d);
        if (lane == 0) sprefix = s;
    }
    __syncthreads();
    int add = sprefix;

    o0 += add; o1 += add; o2 += add; o3 += add;
    if (i0 + 0 < n) a[i0 + 0] = o0;
    if (i0 + 1 < n) a[i0 + 1] = o1;
    if (i0 + 2 < n) a[i0 + 2] = o2;
    if (i0 + 3 < n) a[i0 + 3] = o3;
    if (i0 + 0 < ncur) cur[i0 + 0] = o0;
    if (i0 + 1 < ncur) cur[i0 + 1] = o1;
    if (i0 + 2 < ncur) cur[i0 + 2] = o2;
    if (i0 + 3 < ncur) cur[i0 + 3] = o3;
}

// ---------------------------------------------------------------------------
// fused scatter for both edge lists; 4 edges per thread
// ---------------------------------------------------------------------------
__global__ void k_scatter_both(const int* __restrict__ src1, const int* __restrict__ dst1, int E1,
                               int* __restrict__ cur1, int* __restrict__ adj1, int nb1,
                               const int* __restrict__ src2, const int* __restrict__ dst2, int E2,
                               int* __restrict__ cur2, int* __restrict__ adj2) {
    const int *src, *dst; int E; int *cur, *adj; int b;
    if (blockIdx.x < nb1) { src = src1; dst = dst1; E = E1; cur = cur1; adj = adj1; b = blockIdx.x; }
    else                  { src = src2; dst = dst2; E = E2; cur = cur2; adj = adj2; b = blockIdx.x - nb1; }
    int i = (b * blockDim.x + threadIdx.x) * 4;
    if (i + 4 <= E) {
        int4 s = *(const int4*)(src + i);
        int4 d = *(const int4*)(dst + i);
        int p0 = atomicAdd(&cur[d.x], 1);
        int p1 = atomicAdd(&cur[d.y], 1);
        int p2 = atomicAdd(&cur[d.z], 1);
        int p3 = atomicAdd(&cur[d.w], 1);
        adj[p0] = s.x; adj[p1] = s.y; adj[p2] = s.z; adj[p3] = s.w;
    } else {
        for (int j = i; j < E; ++j) {
            int p = atomicAdd(&cur[dst[j]], 1);
            adj[p] = src[j];
        }
    }
}

// ---------------------------------------------------------------------------
// mean aggregation over fp16 features, fp32 accumulation, fp32 output.
// One warp per row; PL halves per lane (4 or 8); 4 edges per iteration.
// ---------------------------------------------------------------------------
template <int PL>
__global__ void k_agg_mean_h(const __half* __restrict__ feat, const int* __restrict__ adj,
                             const int* __restrict__ off, float* __restrict__ out, int nrows) {
    int row = blockIdx.x * blockDim.y + threadIdx.y;
    if (row >= nrows) return;
    int lane = threadIdx.x;
    const int C = PL * 32;
    int s0 = off[row];
    int s1 = off[row + 1];

    float acc[PL];
    #pragma unroll
    for (int c = 0; c < PL; ++c) acc[c] = 0.f;

    auto accum_row = [&](int idx) {
        const __half* p = feat + (size_t)idx * C + lane * PL;
        if (PL == 8) {
            uint4 raw = *(const uint4*)p;
            const __half2* h = (const __half2*)&raw;
            #pragma unroll
            for (int j = 0; j < 4; ++j) {
                float2 f = __half22float2(h[j]);
                acc[2 * j] += f.x; acc[2 * j + 1] += f.y;
            }
        } else {
            uint2 raw = *(const uint2*)p;
            const __half2* h = (const __half2*)&raw;
            #pragma unroll
            for (int j = 0; j < 2; ++j) {
                float2 f = __half22float2(h[j]);
                acc[2 * j] += f.x; acc[2 * j + 1] += f.y;
            }
        }
    };

    int j = s0;
    for (; j + 4 <= s1; j += 4) {
        int i0 = adj[j], i1 = adj[j + 1], i2 = adj[j + 2], i3 = adj[j + 3];
        accum_row(i0); accum_row(i1); accum_row(i2); accum_row(i3);
    }
    for (; j < s1; ++j) accum_row(adj[j]);

    int deg = s1 - s0;
    float inv = 1.0f / (float)(deg > 0 ? deg : 1);
    float* orow = out + (size_t)row * C + lane * PL;
    #pragma unroll
    for (int v = 0; v < PL; v += 4) {
        float4 r = make_float4(acc[v] * inv, acc[v + 1] * inv, acc[v + 2] * inv, acc[v + 3] * inv);
        *(float4*)(orow + v) = r;
    }
}

// ---------------------------------------------------------------------------
// tf32 tensor-core dual-input GEMM, double-buffered.
//   C[M,N] = [A1(fp32) | A2(fp16)] @ [B1 ; B2] + bias, optional relu.
// OutT = float or __half.
// ---------------------------------------------------------------------------
__device__ __forceinline__ float tf32r(float x) {
    unsigned u;
    asm("cvt.rna.tf32.f32 %0, %1;" : "=r"(u) : "f"(x));
    return __uint_as_float(u);
}

__device__ __forceinline__ void mma_tf32(float* c, const unsigned* a, const unsigned* b) {
    asm volatile(
        "mma.sync.aligned.m16n8k8.row.col.f32.tf32.tf32.f32 "
        "{%0,%1,%2,%3}, {%4,%5,%6,%7}, {%8,%9}, {%0,%1,%2,%3};"
        : "+f"(c[0]), "+f"(c[1]), "+f"(c[2]), "+f"(c[3])
        : "r"(a[0]), "r"(a[1]), "r"(a[2]), "r"(a[3]), "r"(b[0]), "r"(b[1]));
}

__device__ __forceinline__ void store_pair(float* C, size_t off, float a, float b) {
    *(float2*)(C + off) = make_float2(a, b);
}
__device__ __forceinline__ void store_pair(__half* C, size_t off, float a, float b) {
    *(__half2*)(C + off) = __floats2half2_rn(a, b);
}

template <typename OutT>
__global__ void __launch_bounds__(256, 2)
k_gemm_dual_tc(const float* __restrict__ A1, const __half* __restrict__ A2,
               const float* __restrict__ B1, const float* __restrict__ B2,
               const float* __restrict__ bias, OutT* __restrict__ C,
               int M, int K1, int K2, int N, int doRelu) {
    __shared__ float As[2][16 * 136];
    __shared__ float Bs[2][16 * 136];

    int tid  = threadIdx.x;
    int lane = tid & 31;
    int warp = tid >> 5;
    int wm = warp >> 2;
    int wn = warp & 3;
    int g  = lane >> 2;
    int tg = lane & 3;
    int bm = blockIdx.y * 128;
    int bn = blockIdx.x * 128;
    int Ktot = K1 + K2;
    int ntiles = Ktot >> 4;

    float acc[4][4][4];
    #pragma unroll
    for (int mt = 0; mt < 4; ++mt)
        #pragma unroll
        for (int nt = 0; nt < 4; ++nt)
            #pragma unroll
            for (int c = 0; c < 4; ++c) acc[mt][nt][c] = 0.f;

    int am  = tid >> 2;
    int ak4 = (tid & 3) << 2;
    int bk  = tid >> 5;
    int bn4 = (tid & 31) << 2;

    float4 av[2], bv[2];

    auto ldg_tile = [&](int t) {
        int kb = t << 4;
        if (kb < K1) {
            #pragma unroll
            for (int i = 0; i < 2; ++i) {
                int gm = bm + am + 64 * i;
                av[i] = (gm < M) ? *(const float4*)(A1 + (size_t)gm * K1 + kb + ak4)
                                 : make_float4(0.f, 0.f, 0.f, 0.f);
            }
            #pragma unroll
            for (int i = 0; i < 2; ++i) {
                int k = bk + 8 * i;
                bv[i] = *(const float4*)(B1 + (size_t)(kb + k) * N + bn + bn4);
            }
        } else {
            int kcol = kb - K1;
            #pragma unroll
            for (int i = 0; i < 2; ++i) {
                int gm = bm + am + 64 * i;
                if (gm < M) {
                    uint2 raw = *(const uint2*)(A2 + (size_t)gm * K2 + kcol + ak4);
                    const __half2* hp = (const __half2*)&raw;
                    float2 f0 = __half22float2(hp[0]);
                    float2 f1 = __half22float2(hp[1]);
                    av[i] = make_float4(f0.x, f0.y, f1.x, f1.y);
                } else {
                    av[i] = make_float4(0.f, 0.f, 0.f, 0.f);
                }
            }
            #pragma unroll
            for (int i = 0; i < 2; ++i) {
                int k = bk + 8 * i;
                bv[i] = *(const float4*)(B2 + (size_t)(kcol + k) * N + bn + bn4);
            }
        }
    };

    auto sts_tile = [&](int b) {
        #pragma unroll
        for (int i = 0; i < 2; ++i) {
            int m = am + 64 * i;
            float vv[4] = {av[i].x, av[i].y, av[i].z, av[i].w};
            #pragma unroll
            for (int j = 0; j < 4; ++j) {
                int k = ak4 + j;
                As[b][k * 136 + (m ^ ((k >> 2) << 3))] = tf32r(vv[j]);
            }
        }
        #pragma unroll
        for (int i = 0; i < 2; ++i) {
            int k = bk + 8 * i;
            float4 v = bv[i];
            v.x = tf32r(v.x); v.y = tf32r(v.y); v.z = tf32r(v.z); v.w = tf32r(v.w);
            *(float4*)&Bs[b][k * 136 + bn4] = v;
        }
    };

    auto compute_tile = [&](int b) {
        #pragma unroll
        for (int k8 = 0; k8 < 16; k8 += 8) {
            unsigned a[4][4], bb[4][2];
            int kA = k8 + tg;
            int kB = k8 + tg + 4;
            int sA = (kA >> 2) << 3;
            int sB = (kB >> 2) << 3;
            #pragma unroll
            for (int mt = 0; mt < 4; ++mt) {
                int m0 = wm * 64 + mt * 16 + g;
                a[mt][0] = __float_as_uint(As[b][kA * 136 + ( m0      ^ sA)]);
                a[mt][1] = __float_as_uint(As[b][kA * 136 + ((m0 + 8) ^ sA)]);
                a[mt][2] = __float_as_uint(As[b][kB * 136 + ( m0      ^ sB)]);
                a[mt][3] = __float_as_uint(As[b][kB * 136 + ((m0 + 8) ^ sB)]);
            }
            #pragma unroll
            for (int nt = 0; nt < 4; ++nt) {
                int n0 = wn * 32 + nt * 8 + g;
                bb[nt][0] = __float_as_uint(Bs[b][kA * 136 + n0]);
                bb[nt][1] = __float_as_uint(Bs[b][kB * 136 + n0]);
            }
            #pragma unroll
            for (int mt = 0; mt < 4; ++mt)
                #pragma unroll
                for (int nt = 0; nt < 4; ++nt)
                    mma_tf32(acc[mt][nt], a[mt], bb[nt]);
        }
    };

    ldg_tile(0);
    sts_tile(0);
    __syncthreads();

    for (int t = 0; t < ntiles; ++t) {
        int cur = t & 1;
        if (t + 1 < ntiles) ldg_tile(t + 1);
        compute_tile(cur);
        if (t + 1 < ntiles) {
            sts_tile(cur ^ 1);
            __syncthreads();
        }
    }

    #pragma unroll
    for (int nt = 0; nt < 4; ++nt) {
        int col = bn + wn * 32 + nt * 8 + tg * 2;
        float2 bb = *(const float2*)&bias[col];
        #pragma unroll
        for (int mt = 0; mt < 4; ++mt) {
            int row_lo = bm + wm * 64 + mt * 16 + g;
            int row_hi = row_lo + 8;
            float lx = acc[mt][nt][0] + bb.x, ly = acc[mt][nt][1] + bb.y;
            float hx = acc[mt][nt][2] + bb.x, hy = acc[mt][nt][3] + bb.y;
            if (doRelu) {
                lx = fmaxf(lx, 0.f); ly = fmaxf(ly, 0.f);
                hx = fmaxf(hx, 0.f); hy = fmaxf(hy, 0.f);
            }
            if (row_lo < M) store_pair(C, (size_t)row_lo * N + col, lx, ly);
            if (row_hi < M) store_pair(C, (size_t)row_hi * N + col, hx, hy);
        }
    }
}

// ---------------------------------------------------------------------------
// host side
// ---------------------------------------------------------------------------
extern "C" void kernel_launch(void* const* d_in, const int* in_sizes, int n_in,
                              void* d_out, int out_size) {
    (void)in_sizes; (void)n_in; (void)out_size;

    const float* x    = (const float*)d_in[0];
    const int*   src1 = (const int*)d_in[1];
    const int*   dst1 = (const int*)d_in[2];
    const int*   src2 = (const int*)d_in[3];
    const int*   dst2 = (const int*)d_in[4];
    const float* Wl1  = (const float*)d_in[5];
    const float* Wr1  = (const float*)d_in[6];
    const float* b1   = (const float*)d_in[7];
    const float* Wl2  = (const float*)d_in[8];
    const float* Wr2  = (const float*)d_in[9];
    const float* b2   = (const float*)d_in[10];
    float* out = (float*)d_out;

    int *off1, *cur1, *adj1, *off2, *cur2, *adj2, *parts, *counter;
    float *agg1, *agg2;
    __half *xh, *h;
    cudaGetSymbolAddress((void**)&off1, g_off1);
    cudaGetSymbolAddress((void**)&cur1, g_cur1);
    cudaGetSymbolAddress((void**)&adj1, g_adj1);
    cudaGetSymbolAddress((void**)&agg1, g_agg1);
    cudaGetSymbolAddress((void**)&xh,   g_xh);
    cudaGetSymbolAddress((void**)&h,    g_h);
    cudaGetSymbolAddress((void**)&off2, g_off2);
    cudaGetSymbolAddress((void**)&cur2, g_cur2);
    cudaGetSymbolAddress((void**)&adj2, g_adj2);
    cudaGetSymbolAddress((void**)&agg2, g_agg2);
    cudaGetSymbolAddress((void**)&parts, g_parts);
    cudaGetSymbolAddress((void**)&counter, g_scan_counter);

    const int hb1 = (cE1 / 4 + 255) / 256;           // 977
    const int hb2 = (cE2 / 4 + 255) / 256;           // 245
    const int cvb = (cN0 * cCIN) / (256 * 8);        // 12500 (exact)

    // ---- CSR build + x->fp16 convert ----
    k_zero_both<<<(cN1 + 1 + 255) / 256, 256>>>(off1, cN1 + 1, off2, cN2 + 1, counter);
    k_hist_conv<<<hb1 + hb2 + cvb, 256>>>(dst1, cE1, off1, hb1,
                                          dst2, cE2, off2, hb2,
                                          x, xh, cN0 * cCIN);
    k_scan_onepass<<<SB1 + SB2, 256>>>(off1, cN1 + 1, SB1, cur1, cN1,
                                       off2, cN2 + 1, cur2, cN2, parts, counter);
    k_scatter_both<<<hb1 + hb2, 256>>>(src1, dst1, cE1, cur1, adj1, hb1,
                                       src2, dst2, cE2, cur2, adj2);

    // ---- layer 1 ----
    k_agg_mean_h<4><<<(cN1 + 7) / 8, dim3(32, 8)>>>(xh, adj1, off1, agg1, cN1);
    k_gemm_dual_tc<__half><<<dim3(cH / 128, (cN1 + 127) / 128), 256>>>(
        agg1, xh, Wl1, Wr1, b1, h, cN1, cCIN, cCIN, cH, 1);

    // ---- layer 2 ----
    k_agg_mean_h<8><<<(cN2 + 7) / 8, dim3(32, 8)>>>(h, adj2, off2, agg2, cN2);
    k_gemm_dual_tc<float><<<dim3(cH / 128, (cN2 + 127) / 128), 256>>>(
        agg2, h, Wl2, Wr2, b2, out, cN2, cH, cH, cH, 0);
}

// round 13
// speedup vs baseline: 2.9391x; 1.2878x over previous
#include <cuda_runtime.h>
#include <cuda_fp16.h>
#include <cstddef>

// ---------------------------------------------------------------------------
// SAGE 2-layer. R11: full-fp16 tensor-core GEMM (m16n8k16, fp32 accum),
// fp16 weights (== tf32 precision), MLP-8 CSR build, fp16 agg outputs.
// ---------------------------------------------------------------------------

static constexpr int cN0 = 200000;
static constexpr int cN1 = 50000;
static constexpr int cN2 = 10000;
static constexpr int cE1 = 1000000;
static constexpr int cE2 = 250000;
static constexpr int cCIN = 128;
static constexpr int cH = 256;

static constexpr int SCAN_CHUNK = 1024;
static constexpr int SB1 = (cN1 + 1 + SCAN_CHUNK - 1) / SCAN_CHUNK;  // 49
static constexpr int SB2 = (cN2 + 1 + SCAN_CHUNK - 1) / SCAN_CHUNK;  // 10

// ---- static device scratch ----
__device__ int    g_off1[cN1 + 1];
__device__ int    g_cur1[cN1];
__device__ int    g_adj1[cE1];
__device__ __half g_agg1[(size_t)cN1 * cCIN];   // fp16 agg output
__device__ __half g_xh[(size_t)cN0 * cCIN];     // fp16 copy of x
__device__ __half g_h[(size_t)cN1 * cH];        // layer-1 output fp16
__device__ int    g_off2[cN2 + 1];
__device__ int    g_cur2[cN2];
__device__ int    g_adj2[cE2];
__device__ __half g_agg2[(size_t)cN2 * cH];
__device__ int    g_parts[SB1 + SB2];
__device__ int    g_scan_counter;
__device__ __half g_wl1h[cCIN * cH];
__device__ __half g_wr1h[cCIN * cH];
__device__ __half g_wl2h[cH * cH];
__device__ __half g_wr2h[cH * cH];

// ---------------------------------------------------------------------------
// zero off arrays + counter, and convert the 4 weight matrices to fp16
// ---------------------------------------------------------------------------
__global__ void k_zero_wconv(int* __restrict__ p1, int n1, int* __restrict__ p2, int n2,
                             int* __restrict__ counter,
                             const float* __restrict__ Wl1, __half* __restrict__ wl1h,
                             const float* __restrict__ Wr1, __half* __restrict__ wr1h,
                             const float* __restrict__ Wl2, __half* __restrict__ wl2h,
                             const float* __restrict__ Wr2, __half* __restrict__ wr2h) {
    int i = blockIdx.x * blockDim.x + threadIdx.x;
    if (i < n1) p1[i] = 0;
    if (i < n2) p2[i] = 0;
    if (i == 0) *counter = 0;

    const int s1 = cCIN * cH;   // 32768
    const int s2 = cH * cH;     // 65536
    int ci = i * 8;
    const float* src; __half* dst; int base;
    if      (ci < s1)               { src = Wl1; dst = wl1h; base = 0; }
    else if (ci < 2 * s1)           { src = Wr1; dst = wr1h; base = s1; }
    else if (ci < 2 * s1 + s2)      { src = Wl2; dst = wl2h; base = 2 * s1; }
    else if (ci < 2 * s1 + 2 * s2)  { src = Wr2; dst = wr2h; base = 2 * s1 + s2; }
    else return;
    int o = ci - base;
    float4 a = *(const float4*)(src + o);
    float4 c = *(const float4*)(src + o + 4);
    __half2 h0 = __floats2half2_rn(a.x, a.y);
    __half2 h1 = __floats2half2_rn(a.z, a.w);
    __half2 h2 = __floats2half2_rn(c.x, c.y);
    __half2 h3 = __floats2half2_rn(c.z, c.w);
    uint4 packed;
    packed.x = *(unsigned*)&h0; packed.y = *(unsigned*)&h1;
    packed.z = *(unsigned*)&h2; packed.w = *(unsigned*)&h3;
    *(uint4*)(dst + o) = packed;
}

// ---------------------------------------------------------------------------
// fused: x->fp16 conversion (FIRST blocks) + histogram (both layers), 8/thread
// ---------------------------------------------------------------------------
__global__ void k_conv_hist(const float* __restrict__ x, __half* __restrict__ xh, int nx, int ncb,
                            const int* __restrict__ dst1, int E1, int* __restrict__ off1, int nb1,
                            const int* __restrict__ dst2, int E2, int* __restrict__ off2) {
    int b = blockIdx.x;
    if (b < ncb) {
        int i = (b * blockDim.x + threadIdx.x) * 8;
        if (i + 8 <= nx) {
            float4 a = *(const float4*)(x + i);
            float4 c = *(const float4*)(x + i + 4);
            __half2 h0 = __floats2half2_rn(a.x, a.y);
            __half2 h1 = __floats2half2_rn(a.z, a.w);
            __half2 h2 = __floats2half2_rn(c.x, c.y);
            __half2 h3 = __floats2half2_rn(c.z, c.w);
            uint4 packed;
            packed.x = *(unsigned*)&h0; packed.y = *(unsigned*)&h1;
            packed.z = *(unsigned*)&h2; packed.w = *(unsigned*)&h3;
            *(uint4*)(xh + i) = packed;
        }
        return;
    }
    b -= ncb;
    const int* dst; int E; int* off;
    if (b < nb1) { dst = dst1; E = E1; off = off1; }
    else         { dst = dst2; E = E2; off = off2; b -= nb1; }
    int i = (b * blockDim.x + threadIdx.x) * 8;
    if (i + 8 <= E) {
        int4 d0 = *(const int4*)(dst + i);
        int4 d1 = *(const int4*)(dst + i + 4);
        atomicAdd(&off[d0.x + 1], 1);
        atomicAdd(&off[d0.y + 1], 1);
        atomicAdd(&off[d0.z + 1], 1);
        atomicAdd(&off[d0.w + 1], 1);
        atomicAdd(&off[d1.x + 1], 1);
        atomicAdd(&off[d1.y + 1], 1);
        atomicAdd(&off[d1.z + 1], 1);
        atomicAdd(&off[d1.w + 1], 1);
    } else {
        for (int j = i; j < E; ++j) atomicAdd(&off[dst[j] + 1], 1);
    }
}

// ---------------------------------------------------------------------------
// single-pass scan: 59 blocks (single wave), grid rendezvous.
// ---------------------------------------------------------------------------
__global__ void k_scan_onepass(int* __restrict__ a1, int n1, int nb1,
                               int* __restrict__ cur1, int ncur1,
                               int* __restrict__ a2, int n2,
                               int* __restrict__ cur2, int ncur2,
                               int* __restrict__ parts, int* __restrict__ counter) {
    __shared__ int wsum[8];
    __shared__ int sprefix;
    int* a; int n; int* cur; int ncur; int bb; int pbase;
    if ((int)blockIdx.x < nb1) { a = a1; n = n1; cur = cur1; ncur = ncur1; bb = blockIdx.x; pbase = 0; }
    else                       { a = a2; n = n2; cur = cur2; ncur = ncur2; bb = blockIdx.x - nb1; pbase = nb1; }

    int tid = threadIdx.x, lane = tid & 31, wid = tid >> 5;
    int i0 = bb * SCAN_CHUNK + tid * 4;

    int v0 = (i0 + 0 < n) ? a[i0 + 0] : 0;
    int v1 = (i0 + 1 < n) ? a[i0 + 1] : 0;
    int v2 = (i0 + 2 < n) ? a[i0 + 2] : 0;
    int v3 = (i0 + 3 < n) ? a[i0 + 3] : 0;
    int l1 = v0 + v1, l2 = l1 + v2, l3 = l2 + v3;

    int x = l3;
    #pragma unroll
    for (int d = 1; d < 32; d <<= 1) {
        int t = __shfl_up_sync(0xffffffffu, x, d);
        if (lane >= d) x += t;
    }
    if (lane == 31) wsum[wid] = x;
    __syncthreads();
    if (wid == 0 && lane < 8) {
        int s = wsum[lane];
        #pragma unroll
        for (int d = 1; d < 8; d <<= 1) {
            int t = __shfl_up_sync(0x000000ffu, s, d);
            if (lane >= d) s += t;
        }
        wsum[lane] = s;
    }
    __syncthreads();
    int pre = x - l3 + (wid > 0 ? wsum[wid - 1] : 0);
    int o0 = pre + v0, o1 = pre + l1, o2 = pre + l2, o3 = pre + l3;

    if (tid == 255) {
        parts[pbase + bb] = pre + l3;
        __threadfence();
        atomicAdd(counter, 1);
    }
    if (tid == 0) {
        while (atomicAdd(counter, 0) < (int)gridDim.x) { }
    }
    __syncthreads();
    __threadfence();

    if (tid < 32) {
        int s = 0;
        for (int j = lane; j < bb; j += 32) s += parts[pbase + j];
        #pragma unroll
        for (int d = 16; d > 0; d >>= 1) s += __shfl_xor_sync(0xffffffffu, s, d);
        if (lane == 0) sprefix = s;
    }
    __syncthreads();
    int add = sprefix;

    o0 += add; o1 += add; o2 += add; o3 += add;
    if (i0 + 0 < n) a[i0 + 0] = o0;
    if (i0 + 1 < n) a[i0 + 1] = o1;
    if (i0 + 2 < n) a[i0 + 2] = o2;
    if (i0 + 3 < n) a[i0 + 3] = o3;
    if (i0 + 0 < ncur) cur[i0 + 0] = o0;
    if (i0 + 1 < ncur) cur[i0 + 1] = o1;
    if (i0 + 2 < ncur) cur[i0 + 2] = o2;
    if (i0 + 3 < ncur) cur[i0 + 3] = o3;
}

// ---------------------------------------------------------------------------
// fused scatter, 8 edges per thread
// ---------------------------------------------------------------------------
__global__ void k_scatter_both(const int* __restrict__ src1, const int* __restrict__ dst1, int E1,
                               int* __restrict__ cur1, int* __restrict__ adj1, int nb1,
                               const int* __restrict__ src2, const int* __restrict__ dst2, int E2,
                               int* __restrict__ cur2, int* __restrict__ adj2) {
    const int *src, *dst; int E; int *cur, *adj; int b;
    if (blockIdx.x < nb1) { src = src1; dst = dst1; E = E1; cur = cur1; adj = adj1; b = blockIdx.x; }
    else                  { src = src2; dst = dst2; E = E2; cur = cur2; adj = adj2; b = blockIdx.x - nb1; }
    int i = (b * blockDim.x + threadIdx.x) * 8;
    if (i + 8 <= E) {
        int4 s0 = *(const int4*)(src + i);
        int4 s1 = *(const int4*)(src + i + 4);
        int4 d0 = *(const int4*)(dst + i);
        int4 d1 = *(const int4*)(dst + i + 4);
        int p0 = atomicAdd(&cur[d0.x], 1);
        int p1 = atomicAdd(&cur[d0.y], 1);
        int p2 = atomicAdd(&cur[d0.z], 1);
        int p3 = atomicAdd(&cur[d0.w], 1);
        int p4 = atomicAdd(&cur[d1.x], 1);
        int p5 = atomicAdd(&cur[d1.y], 1);
        int p6 = atomicAdd(&cur[d1.z], 1);
        int p7 = atomicAdd(&cur[d1.w], 1);
        adj[p0] = s0.x; adj[p1] = s0.y; adj[p2] = s0.z; adj[p3] = s0.w;
        adj[p4] = s1.x; adj[p5] = s1.y; adj[p6] = s1.z; adj[p7] = s1.w;
    } else {
        for (int j = i; j < E; ++j) {
            int p = atomicAdd(&cur[dst[j]], 1);
            adj[p] = src[j];
        }
    }
}

// ---------------------------------------------------------------------------
// mean aggregation: fp16 in, fp32 accum, fp16 out. One warp per row,
// PL halves per lane (4 or 8), 4 edges per iteration.
// ---------------------------------------------------------------------------
template <int PL>
__global__ void k_agg_mean_h(const __half* __restrict__ feat, const int* __restrict__ adj,
                             const int* __restrict__ off, __half* __restrict__ out, int nrows) {
    int row = blockIdx.x * blockDim.y + threadIdx.y;
    if (row >= nrows) return;
    int lane = threadIdx.x;
    const int C = PL * 32;
    int s0 = off[row];
    int s1 = off[row + 1];

    float acc[PL];
    #pragma unroll
    for (int c = 0; c < PL; ++c) acc[c] = 0.f;

    auto accum_row = [&](int idx) {
        const __half* p = feat + (size_t)idx * C + lane * PL;
        if (PL == 8) {
            uint4 raw = *(const uint4*)p;
            const __half2* h = (const __half2*)&raw;
            #pragma unroll
            for (int j = 0; j < 4; ++j) {
                float2 f = __half22float2(h[j]);
                acc[2 * j] += f.x; acc[2 * j + 1] += f.y;
            }
        } else {
            uint2 raw = *(const uint2*)p;
            const __half2* h = (const __half2*)&raw;
            #pragma unroll
            for (int j = 0; j < 2; ++j) {
                float2 f = __half22float2(h[j]);
                acc[2 * j] += f.x; acc[2 * j + 1] += f.y;
            }
        }
    };

    int j = s0;
    for (; j + 4 <= s1; j += 4) {
        int i0 = adj[j], i1 = adj[j + 1], i2 = adj[j + 2], i3 = adj[j + 3];
        accum_row(i0); accum_row(i1); accum_row(i2); accum_row(i3);
    }
    for (; j < s1; ++j) accum_row(adj[j]);

    int deg = s1 - s0;
    float inv = 1.0f / (float)(deg > 0 ? deg : 1);
    __half* orow = out + (size_t)row * C + lane * PL;
    __half2 r[PL / 2];
    #pragma unroll
    for (int v = 0; v < PL / 2; ++v)
        r[v] = __floats2half2_rn(acc[2 * v] * inv, acc[2 * v + 1] * inv);
    if (PL == 8) *(uint4*)orow = *(uint4*)r;
    else         *(uint2*)orow = *(uint2*)r;
}

// ---------------------------------------------------------------------------
// fp16 tensor-core dual-input GEMM (fp32 accum), double-buffered, BK=32:
//   C[M,N] = [A1 | A2] @ [B1 ; B2] + bias, optional relu.  All operands fp16.
// Block tile 128x128, 256 threads (8 warps 2x4), warp tile 64x32.
// SMEM: As2[k2][m], Bs2[k2][n] as half2 words, stride 136 (frag loads
// conflict-free: bank = 8*tg + g).
// ---------------------------------------------------------------------------
__device__ __forceinline__ void mma_f16(float* c, const unsigned* a, const unsigned* b) {
    asm volatile(
        "mma.sync.aligned.m16n8k16.row.col.f32.f16.f16.f32 "
        "{%0,%1,%2,%3}, {%4,%5,%6,%7}, {%8,%9}, {%0,%1,%2,%3};"
        : "+f"(c[0]), "+f"(c[1]), "+f"(c[2]), "+f"(c[3])
        : "r"(a[0]), "r"(a[1]), "r"(a[2]), "r"(a[3]), "r"(b[0]), "r"(b[1]));
}

__device__ __forceinline__ void store_pair(float* C, size_t off, float a, float b) {
    *(float2*)(C + off) = make_float2(a, b);
}
__device__ __forceinline__ void store_pair(__half* C, size_t off, float a, float b) {
    *(__half2*)(C + off) = __floats2half2_rn(a, b);
}

template <typename OutT>
__global__ void __launch_bounds__(256, 2)
k_gemm_dual_h(const __half* __restrict__ A1, const __half* __restrict__ A2,
              const __half* __restrict__ B1, const __half* __restrict__ B2,
              const float* __restrict__ bias, OutT* __restrict__ C,
              int M, int K1, int K2, int N, int doRelu) {
    __shared__ unsigned As2[2][16 * 136];   // [k2][m], k2 = k/2 within 32-wide tile
    __shared__ unsigned Bs2[2][16 * 136];   // [k2][n]

    int tid  = threadIdx.x;
    int lane = tid & 31;
    int warp = tid >> 5;
    int wm = warp >> 2;
    int wn = warp & 3;
    int g  = lane >> 2;
    int tg = lane & 3;
    int bm = blockIdx.y * 128;
    int bn = blockIdx.x * 128;
    int Ktot = K1 + K2;
    int ntiles = Ktot >> 5;

    float acc[4][4][4];
    #pragma unroll
    for (int mt = 0; mt < 4; ++mt)
        #pragma unroll
        for (int nt = 0; nt < 4; ++nt)
            #pragma unroll
            for (int c = 0; c < 4; ++c) acc[mt][nt][c] = 0.f;

    // staging thread mapping
    int am  = tid >> 1;            // 0..127 A row
    int ah  = (tid & 1) * 16;      // A half-col offset within 32-wide tile
    int bk2 = tid >> 4;            // 0..15 B k-pair row
    int bn8 = (tid & 15) * 8;      // B col start (8 halves)

    uint4 avr0, avr1, bvr0, bvr1;

    auto ldg_tile = [&](int t) {
        int kb = t << 5;
        const __half* Asrc; int ldA, kcol;
        const __half* Bsrc; int kbb;
        if (kb < K1) { Asrc = A1; ldA = K1; kcol = kb;      Bsrc = B1; kbb = kb; }
        else         { Asrc = A2; ldA = K2; kcol = kb - K1; Bsrc = B2; kbb = kb - K1; }
        int gm = bm + am;
        if (gm < M) {
            const __half* ap = Asrc + (size_t)gm * ldA + kcol + ah;
            avr0 = *(const uint4*)ap;
            avr1 = *(const uint4*)(ap + 8);
        } else {
            avr0 = make_uint4(0, 0, 0, 0);
            avr1 = make_uint4(0, 0, 0, 0);
        }
        const __half* bp = Bsrc + (size_t)(kbb + 2 * bk2) * N + bn + bn8;
        bvr0 = *(const uint4*)bp;
        bvr1 = *(const uint4*)(bp + N);
    };

    auto sts_tile = [&](int b) {
        // A: words of avr are already k-consecutive half pairs
        int k2b = ah >> 1;   // 0 or 8
        const unsigned* aw0 = (const unsigned*)&avr0;
        const unsigned* aw1 = (const unsigned*)&avr1;
        #pragma unroll
        for (int j = 0; j < 4; ++j) {
            As2[b][(k2b + j) * 136 + am]     = aw0[j];
            As2[b][(k2b + 4 + j) * 136 + am] = aw1[j];
        }
        // B: interleave rows 2k2 / 2k2+1 into k-pair half2 words
        const unsigned* r0 = (const unsigned*)&bvr0;
        const unsigned* r1 = (const unsigned*)&bvr1;
        unsigned q[8];
        #pragma unroll
        for (int j = 0; j < 4; ++j) {
            q[2 * j]     = __byte_perm(r0[j], r1[j], 0x5410);
            q[2 * j + 1] = __byte_perm(r0[j], r1[j], 0x7632);
        }
        *(uint4*)&Bs2[b][bk2 * 136 + bn8]     = *(uint4*)q;
        *(uint4*)&Bs2[b][bk2 * 136 + bn8 + 4] = *(uint4*)(q + 4);
    };

    auto compute_tile = [&](int b) {
        #pragma unroll
        for (int kg = 0; kg < 2; ++kg) {
            int r0 = kg * 8 + tg;
            int r1 = kg * 8 + tg + 4;
            unsigned a[4][4], bb[4][2];
            #pragma unroll
            for (int mt = 0; mt < 4; ++mt) {
                int m0 = wm * 64 + mt * 16 + g;
                a[mt][0] = As2[b][r0 * 136 + m0];
                a[mt][1] = As2[b][r0 * 136 + m0 + 8];
                a[mt][2] = As2[b][r1 * 136 + m0];
                a[mt][3] = As2[b][r1 * 136 + m0 + 8];
            }
            #pragma unroll
            for (int nt = 0; nt < 4; ++nt) {
                int n0 = wn * 32 + nt * 8 + g;
                bb[nt][0] = Bs2[b][r0 * 136 + n0];
                bb[nt][1] = Bs2[b][r1 * 136 + n0];
            }
            #pragma unroll
            for (int mt = 0; mt < 4; ++mt)
                #pragma unroll
                for (int nt = 0; nt < 4; ++nt)
                    mma_f16(acc[mt][nt], a[mt], bb[nt]);
        }
    };

    ldg_tile(0);
    sts_tile(0);
    __syncthreads();

    for (int t = 0; t < ntiles; ++t) {
        int cur = t & 1;
        if (t + 1 < ntiles) ldg_tile(t + 1);
        compute_tile(cur);
        if (t + 1 < ntiles) {
            sts_tile(cur ^ 1);
            __syncthreads();
        }
    }

    #pragma unroll
    for (int nt = 0; nt < 4; ++nt) {
        int col = bn + wn * 32 + nt * 8 + tg * 2;
        float2 bb = *(const float2*)&bias[col];
        #pragma unroll
        for (int mt = 0; mt < 4; ++mt) {
            int row_lo = bm + wm * 64 + mt * 16 + g;
            int row_hi = row_lo + 8;
            float lx = acc[mt][nt][0] + bb.x, ly = acc[mt][nt][1] + bb.y;
            float hx = acc[mt][nt][2] + bb.x, hy = acc[mt][nt][3] + bb.y;
            if (doRelu) {
                lx = fmaxf(lx, 0.f); ly = fmaxf(ly, 0.f);
                hx = fmaxf(hx, 0.f); hy = fmaxf(hy, 0.f);
            }
            if (row_lo < M) store_pair(C, (size_t)row_lo * N + col, lx, ly);
            if (row_hi < M) store_pair(C, (size_t)row_hi * N + col, hx, hy);
        }
    }
}

// ---------------------------------------------------------------------------
// host side
// ---------------------------------------------------------------------------
extern "C" void kernel_launch(void* const* d_in, const int* in_sizes, int n_in,
                              void* d_out, int out_size) {
    (void)in_sizes; (void)n_in; (void)out_size;

    const float* x    = (const float*)d_in[0];
    const int*   src1 = (const int*)d_in[1];
    const int*   dst1 = (const int*)d_in[2];
    const int*   src2 = (const int*)d_in[3];
    const int*   dst2 = (const int*)d_in[4];
    const float* Wl1  = (const float*)d_in[5];
    const float* Wr1  = (const float*)d_in[6];
    const float* b1   = (const float*)d_in[7];
    const float* Wl2  = (const float*)d_in[8];
    const float* Wr2  = (const float*)d_in[9];
    const float* b2   = (const float*)d_in[10];
    float* out = (float*)d_out;

    int *off1, *cur1, *adj1, *off2, *cur2, *adj2, *parts, *counter;
    __half *agg1, *agg2, *xh, *h, *wl1h, *wr1h, *wl2h, *wr2h;
    cudaGetSymbolAddress((void**)&off1, g_off1);
    cudaGetSymbolAddress((void**)&cur1, g_cur1);
    cudaGetSymbolAddress((void**)&adj1, g_adj1);
    cudaGetSymbolAddress((void**)&agg1, g_agg1);
    cudaGetSymbolAddress((void**)&xh,   g_xh);
    cudaGetSymbolAddress((void**)&h,    g_h);
    cudaGetSymbolAddress((void**)&off2, g_off2);
    cudaGetSymbolAddress((void**)&cur2, g_cur2);
    cudaGetSymbolAddress((void**)&adj2, g_adj2);
    cudaGetSymbolAddress((void**)&agg2, g_agg2);
    cudaGetSymbolAddress((void**)&parts, g_parts);
    cudaGetSymbolAddress((void**)&counter, g_scan_counter);
    cudaGetSymbolAddress((void**)&wl1h, g_wl1h);
    cudaGetSymbolAddress((void**)&wr1h, g_wr1h);
    cudaGetSymbolAddress((void**)&wl2h, g_wl2h);
    cudaGetSymbolAddress((void**)&wr2h, g_wr2h);

    const int hb1 = (cE1 / 8 + 255) / 256;           // 489
    const int hb2 = (cE2 / 8 + 255) / 256;           // 123
    const int cvb = (cN0 * cCIN) / (256 * 8);        // 12500 (exact)
    const int zb  = (cN1 + 1 + 255) / 256;           // 196 (>= 96 weight-conv blocks)

    // ---- setup: zero + weight fp16 convert; x fp16 convert + hist ----
    k_zero_wconv<<<zb, 256>>>(off1, cN1 + 1, off2, cN2 + 1, counter,
                              Wl1, wl1h, Wr1, wr1h, Wl2, wl2h, Wr2, wr2h);
    k_conv_hist<<<cvb + hb1 + hb2, 256>>>(x, xh, cN0 * cCIN, cvb,
                                          dst1, cE1, off1, hb1,
                                          dst2, cE2, off2);
    k_scan_onepass<<<SB1 + SB2, 256>>>(off1, cN1 + 1, SB1, cur1, cN1,
                                       off2, cN2 + 1, cur2, cN2, parts, counter);
    k_scatter_both<<<hb1 + hb2, 256>>>(src1, dst1, cE1, cur1, adj1, hb1,
                                       src2, dst2, cE2, cur2, adj2);

    // ---- layer 1 ----
    k_agg_mean_h<4><<<(cN1 + 7) / 8, dim3(32, 8)>>>(xh, adj1, off1, agg1, cN1);
    k_gemm_dual_h<__half><<<dim3(cH / 128, (cN1 + 127) / 128), 256>>>(
        agg1, xh, wl1h, wr1h, b1, h, cN1, cCIN, cCIN, cH, 1);

    // ---- layer 2 ----
    k_agg_mean_h<8><<<(cN2 + 7) / 8, dim3(32, 8)>>>(h, adj2, off2, agg2, cN2);
    k_gemm_dual_h<float><<<dim3(cH / 128, (cN2 + 127) / 128), 256>>>(
        agg2, h, wl2h, wr2h, b2, out, cN2, cH, cH, cH, 0);
}

// round 14
// speedup vs baseline: 3.0142x; 1.0255x over previous
#include <cuda_runtime.h>
#include <cuda_fp16.h>
#include <cstddef>

// ---------------------------------------------------------------------------
// SAGE 2-layer. R13: ldmatrix-based fp16 GEMM ([m][k]/[n][k] swizzled smem,
// LDSM.x4 fragments, weights pre-transposed to [n][k] in setup kernel).
// ---------------------------------------------------------------------------

static constexpr int cN0 = 200000;
static constexpr int cN1 = 50000;
static constexpr int cN2 = 10000;
static constexpr int cE1 = 1000000;
static constexpr int cE2 = 250000;
static constexpr int cCIN = 128;
static constexpr int cH = 256;

static constexpr int SCAN_CHUNK = 1024;
static constexpr int SB1 = (cN1 + 1 + SCAN_CHUNK - 1) / SCAN_CHUNK;  // 49
static constexpr int SB2 = (cN2 + 1 + SCAN_CHUNK - 1) / SCAN_CHUNK;  // 10

// ---- static device scratch ----
__device__ int    g_off1[cN1 + 1];
__device__ int    g_cur1[cN1];
__device__ int    g_adj1[cE1];
__device__ __half g_agg1[(size_t)cN1 * cCIN];
__device__ __half g_xh[(size_t)cN0 * cCIN];
__device__ __half g_h[(size_t)cN1 * cH];
__device__ int    g_off2[cN2 + 1];
__device__ int    g_cur2[cN2];
__device__ int    g_adj2[cE2];
__device__ __half g_agg2[(size_t)cN2 * cH];
__device__ int    g_parts[SB1 + SB2];
__device__ int    g_scan_counter;
// transposed fp16 weights: wt[n*K + k] = W[k*N + n]
__device__ __half g_wl1t[cH * cCIN];   // [256][128]
__device__ __half g_wr1t[cH * cCIN];
__device__ __half g_wl2t[cH * cH];     // [256][256]
__device__ __half g_wr2t[cH * cH];

// ---------------------------------------------------------------------------
// setup: blocks [0,192) transpose weights fp32->fp16 [n][k]; rest zero offs.
// ---------------------------------------------------------------------------
__global__ void k_setup(const float* __restrict__ Wl1, __half* __restrict__ wl1t,
                        const float* __restrict__ Wr1, __half* __restrict__ wr1t,
                        const float* __restrict__ Wl2, __half* __restrict__ wl2t,
                        const float* __restrict__ Wr2, __half* __restrict__ wr2t,
                        int* __restrict__ off1, int n1, int* __restrict__ off2, int n2,
                        int* __restrict__ counter) {
    const int NT1 = (cCIN / 32) * (cH / 32);   // 32 tiles per layer-1 matrix
    const int NT2 = (cH / 32) * (cH / 32);     // 64 tiles per layer-2 matrix
    int t = blockIdx.x;
    if (t < 2 * NT1 + 2 * NT2) {
        const float* W; __half* wt; int K, tile;
        if      (t < NT1)             { W = Wl1; wt = wl1t; K = cCIN; tile = t; }
        else if (t < 2 * NT1)         { W = Wr1; wt = wr1t; K = cCIN; tile = t - NT1; }
        else if (t < 2 * NT1 + NT2)   { W = Wl2; wt = wl2t; K = cH;   tile = t - 2 * NT1; }
        else                          { W = Wr2; wt = wr2t; K = cH;   tile = t - 2 * NT1 - NT2; }
        int ktiles = K / 32;
        int k0 = (tile % ktiles) * 32;
        int n0 = (tile / ktiles) * 32;
        __shared__ float tileS[32][33];
        int tx = threadIdx.x & 31, ty = threadIdx.x >> 5;   // 32 x 8
        #pragma unroll
        for (int i = 0; i < 4; ++i)
            tileS[ty + 8 * i][tx] = W[(size_t)(k0 + ty + 8 * i) * cH + n0 + tx];
        __syncthreads();
        #pragma unroll
        for (int i = 0; i < 4; ++i)
            wt[(size_t)(n0 + ty + 8 * i) * K + k0 + tx] = __float2half_rn(tileS[tx][ty + 8 * i]);
        return;
    }
    int zi = (t - (2 * NT1 + 2 * NT2)) * blockDim.x + threadIdx.x;
    if (zi < n1) off1[zi] = 0;
    if (zi < n2) off2[zi] = 0;
    if (zi == 0) *counter = 0;
}

// ---------------------------------------------------------------------------
// fused: x->fp16 conversion (first blocks) + histogram (both layers)
// ---------------------------------------------------------------------------
__global__ void k_conv_hist(const float* __restrict__ x, __half* __restrict__ xh, int nx, int ncb,
                            const int* __restrict__ dst1, int E1, int* __restrict__ off1, int nb1,
                            const int* __restrict__ dst2, int E2, int* __restrict__ off2) {
    int b = blockIdx.x;
    if (b < ncb) {
        int i = (b * blockDim.x + threadIdx.x) * 8;
        if (i + 8 <= nx) {
            float4 a = *(const float4*)(x + i);
            float4 c = *(const float4*)(x + i + 4);
            __half2 h0 = __floats2half2_rn(a.x, a.y);
            __half2 h1 = __floats2half2_rn(a.z, a.w);
            __half2 h2 = __floats2half2_rn(c.x, c.y);
            __half2 h3 = __floats2half2_rn(c.z, c.w);
            uint4 packed;
            packed.x = *(unsigned*)&h0; packed.y = *(unsigned*)&h1;
            packed.z = *(unsigned*)&h2; packed.w = *(unsigned*)&h3;
            *(uint4*)(xh + i) = packed;
        }
        return;
    }
    b -= ncb;
    const int* dst; int E; int* off;
    if (b < nb1) { dst = dst1; E = E1; off = off1; }
    else         { dst = dst2; E = E2; off = off2; b -= nb1; }
    int i = (b * blockDim.x + threadIdx.x) * 8;
    if (i + 8 <= E) {
        int4 d0 = *(const int4*)(dst + i);
        int4 d1 = *(const int4*)(dst + i + 4);
        atomicAdd(&off[d0.x + 1], 1);
        atomicAdd(&off[d0.y + 1], 1);
        atomicAdd(&off[d0.z + 1], 1);
        atomicAdd(&off[d0.w + 1], 1);
        atomicAdd(&off[d1.x + 1], 1);
        atomicAdd(&off[d1.y + 1], 1);
        atomicAdd(&off[d1.z + 1], 1);
        atomicAdd(&off[d1.w + 1], 1);
    } else {
        for (int j = i; j < E; ++j) atomicAdd(&off[dst[j] + 1], 1);
    }
}

// ---------------------------------------------------------------------------
// single-pass scan (59 blocks, single wave, grid rendezvous)
// ---------------------------------------------------------------------------
__global__ void k_scan_onepass(int* __restrict__ a1, int n1, int nb1,
                               int* __restrict__ cur1, int ncur1,
                               int* __restrict__ a2, int n2,
                               int* __restrict__ cur2, int ncur2,
                               int* __restrict__ parts, int* __restrict__ counter) {
    __shared__ int wsum[8];
    __shared__ int sprefix;
    int* a; int n; int* cur; int ncur; int bb; int pbase;
    if ((int)blockIdx.x < nb1) { a = a1; n = n1; cur = cur1; ncur = ncur1; bb = blockIdx.x; pbase = 0; }
    else                       { a = a2; n = n2; cur = cur2; ncur = ncur2; bb = blockIdx.x - nb1; pbase = nb1; }

    int tid = threadIdx.x, lane = tid & 31, wid = tid >> 5;
    int i0 = bb * SCAN_CHUNK + tid * 4;

    int v0 = (i0 + 0 < n) ? a[i0 + 0] : 0;
    int v1 = (i0 + 1 < n) ? a[i0 + 1] : 0;
    int v2 = (i0 + 2 < n) ? a[i0 + 2] : 0;
    int v3 = (i0 + 3 < n) ? a[i0 + 3] : 0;
    int l1 = v0 + v1, l2 = l1 + v2, l3 = l2 + v3;

    int x = l3;
    #pragma unroll
    for (int d = 1; d < 32; d <<= 1) {
        int t = __shfl_up_sync(0xffffffffu, x, d);
        if (lane >= d) x += t;
    }
    if (lane == 31) wsum[wid] = x;
    __syncthreads();
    if (wid == 0 && lane < 8) {
        int s = wsum[lane];
        #pragma unroll
        for (int d = 1; d < 8; d <<= 1) {
            int t = __shfl_up_sync(0x000000ffu, s, d);
            if (lane >= d) s += t;
        }
        wsum[lane] = s;
    }
    __syncthreads();
    int pre = x - l3 + (wid > 0 ? wsum[wid - 1] : 0);
    int o0 = pre + v0, o1 = pre + l1, o2 = pre + l2, o3 = pre + l3;

    if (tid == 255) {
        parts[pbase + bb] = pre + l3;
        __threadfence();
        atomicAdd(counter, 1);
    }
    if (tid == 0) {
        while (atomicAdd(counter, 0) < (int)gridDim.x) { }
    }
    __syncthreads();
    __threadfence();

    if (tid < 32) {
        int s = 0;
        for (int j = lane; j < bb; j += 32) s += parts[pbase + j];
        #pragma unroll
        for (int d = 16; d > 0; d >>= 1) s += __shfl_xor_sync(0xffffffffu, s, d);
        if (lane == 0) sprefix = s;
    }
    __syncthreads();
    int add = sprefix;

    o0 += add; o1 += add; o2 += add; o3 += add;
    if (i0 + 0 < n) a[i0 + 0] = o0;
    if (i0 + 1 < n) a[i0 + 1] = o1;
    if (i0 + 2 < n) a[i0 + 2] = o2;
    if (i0 + 3 < n) a[i0 + 3] = o3;
    if (i0 + 0 < ncur) cur[i0 + 0] = o0;
    if (i0 + 1 < ncur) cur[i0 + 1] = o1;
    if (i0 + 2 < ncur) cur[i0 + 2] = o2;
    if (i0 + 3 < ncur) cur[i0 + 3] = o3;
}

// ---------------------------------------------------------------------------
// fused scatter, 8 edges per thread
// ---------------------------------------------------------------------------
__global__ void k_scatter_both(const int* __restrict__ src1, const int* __restrict__ dst1, int E1,
                               int* __restrict__ cur1, int* __restrict__ adj1, int nb1,
                               const int* __restrict__ src2, const int* __restrict__ dst2, int E2,
                               int* __restrict__ cur2, int* __restrict__ adj2) {
    const int *src, *dst; int E; int *cur, *adj; int b;
    if (blockIdx.x < nb1) { src = src1; dst = dst1; E = E1; cur = cur1; adj = adj1; b = blockIdx.x; }
    else                  { src = src2; dst = dst2; E = E2; cur = cur2; adj = adj2; b = blockIdx.x - nb1; }
    int i = (b * blockDim.x + threadIdx.x) * 8;
    if (i + 8 <= E) {
        int4 s0 = *(const int4*)(src + i);
        int4 s1 = *(const int4*)(src + i + 4);
        int4 d0 = *(const int4*)(dst + i);
        int4 d1 = *(const int4*)(dst + i + 4);
        int p0 = atomicAdd(&cur[d0.x], 1);
        int p1 = atomicAdd(&cur[d0.y], 1);
        int p2 = atomicAdd(&cur[d0.z], 1);
        int p3 = atomicAdd(&cur[d0.w], 1);
        int p4 = atomicAdd(&cur[d1.x], 1);
        int p5 = atomicAdd(&cur[d1.y], 1);
        int p6 = atomicAdd(&cur[d1.z], 1);
        int p7 = atomicAdd(&cur[d1.w], 1);
        adj[p0] = s0.x; adj[p1] = s0.y; adj[p2] = s0.z; adj[p3] = s0.w;
        adj[p4] = s1.x; adj[p5] = s1.y; adj[p6] = s1.z; adj[p7] = s1.w;
    } else {
        for (int j = i; j < E; ++j) {
            int p = atomicAdd(&cur[dst[j]], 1);
            adj[p] = src[j];
        }
    }
}

// ---------------------------------------------------------------------------
// mean aggregation: fp16 in, fp32 accum, fp16 out.
// ---------------------------------------------------------------------------
template <int PL>
__global__ void k_agg_mean_h(const __half* __restrict__ feat, const int* __restrict__ adj,
                             const int* __restrict__ off, __half* __restrict__ out, int nrows) {
    int row = blockIdx.x * blockDim.y + threadIdx.y;
    if (row >= nrows) return;
    int lane = threadIdx.x;
    const int C = PL * 32;
    int s0 = off[row];
    int s1 = off[row + 1];

    float acc[PL];
    #pragma unroll
    for (int c = 0; c < PL; ++c) acc[c] = 0.f;

    auto accum_row = [&](int idx) {
        const __half* p = feat + (size_t)idx * C + lane * PL;
        if (PL == 8) {
            uint4 raw = *(const uint4*)p;
            const __half2* h = (const __half2*)&raw;
            #pragma unroll
            for (int j = 0; j < 4; ++j) {
                float2 f = __half22float2(h[j]);
                acc[2 * j] += f.x; acc[2 * j + 1] += f.y;
            }
        } else {
            uint2 raw = *(const uint2*)p;
            const __half2* h = (const __half2*)&raw;
            #pragma unroll
            for (int j = 0; j < 2; ++j) {
                float2 f = __half22float2(h[j]);
                acc[2 * j] += f.x; acc[2 * j + 1] += f.y;
            }
        }
    };

    int j = s0;
    for (; j + 4 <= s1; j += 4) {
        int i0 = adj[j], i1 = adj[j + 1], i2 = adj[j + 2], i3 = adj[j + 3];
        accum_row(i0); accum_row(i1); accum_row(i2); accum_row(i3);
    }
    for (; j < s1; ++j) accum_row(adj[j]);

    int deg = s1 - s0;
    float inv = 1.0f / (float)(deg > 0 ? deg : 1);
    __half* orow = out + (size_t)row * C + lane * PL;
    __half2 r[PL / 2];
    #pragma unroll
    for (int v = 0; v < PL / 2; ++v)
        r[v] = __floats2half2_rn(acc[2 * v] * inv, acc[2 * v + 1] * inv);
    if (PL == 8) *(uint4*)orow = *(uint4*)r;
    else         *(uint2*)orow = *(uint2*)r;
}

// ---------------------------------------------------------------------------
// fp16 GEMM with ldmatrix fragments, double-buffered, BK=32.
//   C[M,N] = [A1 | A2] @ [B1 ; B2]^T-layout + bias, optional relu.
// A*: [M][K*] fp16 row-major. B*: [N][K*] fp16 row-major (pre-transposed W).
// SMEM tiles [row][k] 128x32 fp16 with 16B-chunk swizzle: chunk ^= (row>>1)&3.
// Fragments via ldmatrix.m8n8.x4 (A: 4/warp/k16, B: 2/warp/k16).
// ---------------------------------------------------------------------------
__device__ __forceinline__ void mma_f16(float* c, const unsigned* a, const unsigned* b) {
    asm volatile(
        "mma.sync.aligned.m16n8k16.row.col.f32.f16.f16.f32 "
        "{%0,%1,%2,%3}, {%4,%5,%6,%7}, {%8,%9}, {%0,%1,%2,%3};"
        : "+f"(c[0]), "+f"(c[1]), "+f"(c[2]), "+f"(c[3])
        : "r"(a[0]), "r"(a[1]), "r"(a[2]), "r"(a[3]), "r"(b[0]), "r"(b[1]));
}

__device__ __forceinline__ void ldsm_x4(unsigned* r, unsigned addr) {
    asm volatile("ldmatrix.sync.aligned.m8n8.x4.shared.b16 {%0,%1,%2,%3}, [%4];"
        : "=r"(r[0]), "=r"(r[1]), "=r"(r[2]), "=r"(r[3]) : "r"(addr));
}

__device__ __forceinline__ void store_pair(float* C, size_t off, float a, float b) {
    *(float2*)(C + off) = make_float2(a, b);
}
__device__ __forceinline__ void store_pair(__half* C, size_t off, float a, float b) {
    *(__half2*)(C + off) = __floats2half2_rn(a, b);
}

template <typename OutT>
__global__ void __launch_bounds__(256, 2)
k_gemm_dual_h(const __half* __restrict__ A1, const __half* __restrict__ A2,
              const __half* __restrict__ B1, const __half* __restrict__ B2,
              const float* __restrict__ bias, OutT* __restrict__ C,
              int M, int K1, int K2, int N, int doRelu) {
    __shared__ __align__(16) __half As[2][128 * 32];
    __shared__ __align__(16) __half Bs[2][128 * 32];

    int tid  = threadIdx.x;
    int lane = tid & 31;
    int warp = tid >> 5;
    int wm = warp >> 2;        // 0..1
    int wn = warp & 3;         // 0..3
    int g  = lane >> 2;
    int tg = lane & 3;
    int bm = blockIdx.y * 128;
    int bn = blockIdx.x * 128;
    int Ktot = K1 + K2;
    int ntiles = Ktot >> 5;

    float acc[4][4][4];
    #pragma unroll
    for (int mt = 0; mt < 4; ++mt)
        #pragma unroll
        for (int nt = 0; nt < 4; ++nt)
            #pragma unroll
            for (int c = 0; c < 4; ++c) acc[mt][nt][c] = 0.f;

    // staging mapping: m = tid>>1 (0..127), h = tid&1 (k-half 0/16)
    int sm = tid >> 1;
    int sh = tid & 1;
    int ssw = (sm >> 1) & 3;

    // ldmatrix lane offsets
    int mA  = (lane & 7) | (((lane >> 3) & 1) << 3);   // row within 16
    int kcA = (lane >> 4) & 1;                          // k-chunk 0/1 within k16
    int nB  = (lane & 7) | (((lane >> 4) & 1) << 3);
    int kcB = (lane >> 3) & 1;

    unsigned asAddr = (unsigned)__cvta_generic_to_shared(&As[0][0]);
    unsigned bsAddr = (unsigned)__cvta_generic_to_shared(&Bs[0][0]);

    uint4 avr0, avr1, bvr0, bvr1;

    auto ldg_tile = [&](int t) {
        int kb = t << 5;
        const __half *Asrc, *Bsrc; int ld, kcol;
        if (kb < K1) { Asrc = A1; Bsrc = B1; ld = K1; kcol = kb; }
        else         { Asrc = A2; Bsrc = B2; ld = K2; kcol = kb - K1; }
        int gm = bm + sm;
        if (gm < M) {
            const __half* ap = Asrc + (size_t)gm * ld + kcol + sh * 16;
            avr0 = *(const uint4*)ap;
            avr1 = *(const uint4*)(ap + 8);
        } else {
            avr0 = make_uint4(0, 0, 0, 0);
            avr1 = make_uint4(0, 0, 0, 0);
        }
        const __half* bp = Bsrc + (size_t)(bn + sm) * ld + kcol + sh * 16;
        bvr0 = *(const uint4*)bp;
        bvr1 = *(const uint4*)(bp + 8);
    };

    auto sts_tile = [&](int b) {
        int c0 = (2 * sh) ^ ssw;
        int c1 = (2 * sh + 1) ^ ssw;
        *(uint4*)&As[b][sm * 32 + c0 * 8] = avr0;
        *(uint4*)&As[b][sm * 32 + c1 * 8] = avr1;
        *(uint4*)&Bs[b][sm * 32 + c0 * 8] = bvr0;
        *(uint4*)&Bs[b][sm * 32 + c1 * 8] = bvr1;
    };

    auto compute_tile = [&](int b) {
        unsigned aB = asAddr + b * 8192;
        unsigned bB = bsAddr + b * 8192;
        #pragma unroll
        for (int kg = 0; kg < 2; ++kg) {
            unsigned af[4][4], bf[2][4];
            #pragma unroll
            for (int mt = 0; mt < 4; ++mt) {
                int m = wm * 64 + mt * 16 + mA;
                int ch = ((kg << 1) | kcA) ^ ((m >> 1) & 3);
                ldsm_x4(af[mt], aB + m * 64 + ch * 16);
            }
            #pragma unroll
            for (int p = 0; p < 2; ++p) {
                int n = wn * 32 + p * 16 + nB;
                int ch = ((kg << 1) | kcB) ^ ((n >> 1) & 3);
                ldsm_x4(bf[p], bB + n * 64 + ch * 16);
            }
            #pragma unroll
            for (int mt = 0; mt < 4; ++mt)
                #pragma unroll
                for (int nt = 0; nt < 4; ++nt)
                    mma_f16(acc[mt][nt], af[mt], &bf[nt >> 1][(nt & 1) << 1]);
        }
    };

    ldg_tile(0);
    sts_tile(0);
    __syncthreads();

    for (int t = 0; t < ntiles; ++t) {
        int cur = t & 1;
        if (t + 1 < ntiles) ldg_tile(t + 1);
        compute_tile(cur);
        if (t + 1 < ntiles) {
            sts_tile(cur ^ 1);
            __syncthreads();
        }
    }

    #pragma unroll
    for (int nt = 0; nt < 4; ++nt) {
        int col = bn + wn * 32 + nt * 8 + tg * 2;
        float2 bb = *(const float2*)&bias[col];
        #pragma unroll
        for (int mt = 0; mt < 4; ++mt) {
            int row_lo = bm + wm * 64 + mt * 16 + g;
            int row_hi = row_lo + 8;
            float lx = acc[mt][nt][0] + bb.x, ly = acc[mt][nt][1] + bb.y;
            float hx = acc[mt][nt][2] + bb.x, hy = acc[mt][nt][3] + bb.y;
            if (doRelu) {
                lx = fmaxf(lx, 0.f); ly = fmaxf(ly, 0.f);
                hx = fmaxf(hx, 0.f); hy = fmaxf(hy, 0.f);
            }
            if (row_lo < M) store_pair(C, (size_t)row_lo * N + col, lx, ly);
            if (row_hi < M) store_pair(C, (size_t)row_hi * N + col, hx, hy);
        }
    }
}

// ---------------------------------------------------------------------------
// host side
// ---------------------------------------------------------------------------
extern "C" void kernel_launch(void* const* d_in, const int* in_sizes, int n_in,
                              void* d_out, int out_size) {
    (void)in_sizes; (void)n_in; (void)out_size;

    const float* x    = (const float*)d_in[0];
    const int*   src1 = (const int*)d_in[1];
    const int*   dst1 = (const int*)d_in[2];
    const int*   src2 = (const int*)d_in[3];
    const int*   dst2 = (const int*)d_in[4];
    const float* Wl1  = (const float*)d_in[5];
    const float* Wr1  = (const float*)d_in[6];
    const float* b1   = (const float*)d_in[7];
    const float* Wl2  = (const float*)d_in[8];
    const float* Wr2  = (const float*)d_in[9];
    const float* b2   = (const float*)d_in[10];
    float* out = (float*)d_out;

    int *off1, *cur1, *adj1, *off2, *cur2, *adj2, *parts, *counter;
    __half *agg1, *agg2, *xh, *h, *wl1t, *wr1t, *wl2t, *wr2t;
    cudaGetSymbolAddress((void**)&off1, g_off1);
    cudaGetSymbolAddress((void**)&cur1, g_cur1);
    cudaGetSymbolAddress((void**)&adj1, g_adj1);
    cudaGetSymbolAddress((void**)&agg1, g_agg1);
    cudaGetSymbolAddress((void**)&xh,   g_xh);
    cudaGetSymbolAddress((void**)&h,    g_h);
    cudaGetSymbolAddress((void**)&off2, g_off2);
    cudaGetSymbolAddress((void**)&cur2, g_cur2);
    cudaGetSymbolAddress((void**)&adj2, g_adj2);
    cudaGetSymbolAddress((void**)&agg2, g_agg2);
    cudaGetSymbolAddress((void**)&parts, g_parts);
    cudaGetSymbolAddress((void**)&counter, g_scan_counter);
    cudaGetSymbolAddress((void**)&wl1t, g_wl1t);
    cudaGetSymbolAddress((void**)&wr1t, g_wr1t);
    cudaGetSymbolAddress((void**)&wl2t, g_wl2t);
    cudaGetSymbolAddress((void**)&wr2t, g_wr2t);

    const int hb1 = (cE1 / 8 + 255) / 256;           // 489
    const int hb2 = (cE2 / 8 + 255) / 256;           // 123
    const int cvb = (cN0 * cCIN) / (256 * 8);        // 12500 (exact)
    const int ntr = 2 * 32 + 2 * 64;                 // 192 transpose tiles
    const int nzb = (cN1 + 1 + 255) / 256;           // 196 zero blocks

    // ---- setup: weight transpose fp16 + zero offs; x fp16 convert + hist ----
    k_setup<<<ntr + nzb, 256>>>(Wl1, wl1t, Wr1, wr1t, Wl2, wl2t, Wr2, wr2t,
                                off1, cN1 + 1, off2, cN2 + 1, counter);
    k_conv_hist<<<cvb + hb1 + hb2, 256>>>(x, xh, cN0 * cCIN, cvb,
                                          dst1, cE1, off1, hb1,
                                          dst2, cE2, off2);
    k_scan_onepass<<<SB1 + SB2, 256>>>(off1, cN1 + 1, SB1, cur1, cN1,
                                       off2, cN2 + 1, cur2, cN2, parts, counter);
    k_scatter_both<<<hb1 + hb2, 256>>>(src1, dst1, cE1, cur1, adj1, hb1,
                                       src2, dst2, cE2, cur2, adj2);

    // ---- layer 1 ----
    k_agg_mean_h<4><<<(cN1 + 7) / 8, dim3(32, 8)>>>(xh, adj1, off1, agg1, cN1);
    k_gemm_dual_h<__half><<<dim3(cH / 128, (cN1 + 127) / 128), 256>>>(
        agg1, xh, wl1t, wr1t, b1, h, cN1, cCIN, cCIN, cH, 1);

    // ---- layer 2 ----
    k_agg_mean_h<8><<<(cN2 + 7) / 8, dim3(32, 8)>>>(h, adj2, off2, agg2, cN2);
    k_gemm_dual_h<float><<<dim3(cH / 128, (cN2 + 127) / 128), 256>>>(
        agg2, h, wl2t, wr2t, b2, out, cN2, cH, cH, cH, 0);
}